// round 11
// baseline (speedup 1.0000x reference)
#include <cuda_runtime.h>
#include <math.h>

// ---------------- problem constants ----------------
#define B_TOK 16384
#define H     1024
#define P2    64      // 2P
#define NE    8
#define EC    32      // E*C pilots
#define NSLOT (2*B_TOK)

// ---------------- device scratch (static; no allocations allowed) ----------------
__device__ float g_x[B_TOK * H];          // layernorm output
__device__ float g_q[B_TOK * H];          // qproj output, then l2-normalized in place
__device__ float g_pn[EC * H];            // normalized pilots
__device__ int   g_te[B_TOK * 2];         // top-2 expert ids per token
__device__ float g_tw[B_TOK * 2];         // top-2 weights per token
__device__ int   g_counts[NE];
__device__ int   g_base[NE];
__device__ int   g_cursor[NE];
__device__ int   g_tokmap[NSLOT];
__device__ float g_wmap[NSLOT];
__device__ float g_hh[(NSLOT + 64) * H];  // expert layer-1 activations (post-relu)
__device__ float g_sh[B_TOK * H];         // shared expert layer-1 activations
__device__ float g_routed[B_TOK * P2];
__device__ float g_sharedout[B_TOK * P2];

// ---------------- reset ----------------
__global__ void reset_kernel() {
    int idx = blockIdx.x * blockDim.x + threadIdx.x;
    if (idx < B_TOK * P2) g_routed[idx] = 0.0f;
    if (idx < NE) g_counts[idx] = 0;
}

// ---------------- layernorm (warp per row) ----------------
__global__ void ln_kernel(const float* __restrict__ mm,
                          const float* __restrict__ gamma,
                          const float* __restrict__ beta) {
    int warp = (blockIdx.x * blockDim.x + threadIdx.x) >> 5;
    int lane = threadIdx.x & 31;
    if (warp >= B_TOK) return;
    const float* row = mm + (size_t)warp * H;
    float s = 0.f, s2 = 0.f;
    for (int i = lane; i < H; i += 32) { float v = row[i]; s += v; s2 += v * v; }
    for (int o = 16; o; o >>= 1) {
        s  += __shfl_xor_sync(0xffffffff, s, o);
        s2 += __shfl_xor_sync(0xffffffff, s2, o);
    }
    float mean = s * (1.0f / H);
    float var  = s2 * (1.0f / H) - mean * mean;
    float inv  = rsqrtf(var + 1e-5f);
    float* out = g_x + (size_t)warp * H;
    for (int i = lane; i < H; i += 32)
        out[i] = (row[i] - mean) * inv * gamma[i] + beta[i];
}

// ---------------- pilot l2 normalize (warp per pilot, 32 pilots) ----------------
__global__ void pilot_norm_kernel(const float* __restrict__ pe) {
    int warp = threadIdx.x >> 5;
    int lane = threadIdx.x & 31;
    const float* row = pe + (size_t)warp * H;
    float s2 = 0.f;
    for (int i = lane; i < H; i += 32) { float v = row[i]; s2 += v * v; }
    for (int o = 16; o; o >>= 1) s2 += __shfl_xor_sync(0xffffffff, s2, o);
    float inv = 1.0f / fmaxf(sqrtf(s2), 1e-12f);
    for (int i = lane; i < H; i += 32) g_pn[warp * H + i] = row[i] * inv;
}

// ---------------- l2 normalize q rows in place (warp per row) ----------------
__global__ void l2q_kernel() {
    int warp = (blockIdx.x * blockDim.x + threadIdx.x) >> 5;
    int lane = threadIdx.x & 31;
    if (warp >= B_TOK) return;
    float* row = g_q + (size_t)warp * H;
    float s2 = 0.f;
    for (int i = lane; i < H; i += 32) { float v = row[i]; s2 += v * v; }
    for (int o = 16; o; o >>= 1) s2 += __shfl_xor_sync(0xffffffff, s2, o);
    float inv = 1.0f / fmaxf(sqrtf(s2), 1e-12f);
    for (int i = lane; i < H; i += 32) row[i] *= inv;
}

// ---------------- router: sims, softmax/temp, top2, counts (warp per token) ---
__global__ void router_kernel() {
    int warp = (blockIdx.x * blockDim.x + threadIdx.x) >> 5;
    int lane = threadIdx.x & 31;
    if (warp >= B_TOK) return;
    const float* q = g_q + (size_t)warp * H;

    float acc[EC];
#pragma unroll
    for (int ec = 0; ec < EC; ec++) acc[ec] = 0.f;

    for (int h = lane; h < H; h += 32) {
        float qv = q[h];
#pragma unroll
        for (int ec = 0; ec < EC; ec++) acc[ec] += qv * g_pn[ec * H + h];
    }

    float sc[NE];
#pragma unroll
    for (int e = 0; e < NE; e++) sc[e] = 0.f;
#pragma unroll
    for (int ec = 0; ec < EC; ec++) {
        float v = acc[ec];
        for (int o = 16; o; o >>= 1) v += __shfl_xor_sync(0xffffffff, v, o);
        sc[ec >> 2] += v * 0.25f;
    }

    // softmax(scores / 0.1)
    float m = -1e30f;
#pragma unroll
    for (int e = 0; e < NE; e++) m = fmaxf(m, sc[e]);
    float p[NE], sum = 0.f;
#pragma unroll
    for (int e = 0; e < NE; e++) { p[e] = expf((sc[e] - m) * 10.f); sum += p[e]; }

    // top-2 on scores (monotone with probs); strict > => lowest index wins ties (jax semantics)
    int i1 = 0;
#pragma unroll
    for (int e = 1; e < NE; e++) if (sc[e] > sc[i1]) i1 = e;
    int i2 = (i1 == 0) ? 1 : 0;
#pragma unroll
    for (int e = 0; e < NE; e++) if (e != i1 && sc[e] > sc[i2]) i2 = e;

    float w1 = p[i1] / sum, w2 = p[i2] / sum;
    float d = w1 + w2 + 1e-6f;
    w1 /= d; w2 /= d;

    if (lane == 0) {
        g_te[warp * 2 + 0] = i1; g_te[warp * 2 + 1] = i2;
        g_tw[warp * 2 + 0] = w1; g_tw[warp * 2 + 1] = w2;
        atomicAdd(&g_counts[i1], 1);
        atomicAdd(&g_counts[i2], 1);
    }
}

// ---------------- scan over 8 experts ----------------
__global__ void scan_kernel() {
    int b = 0;
    for (int e = 0; e < NE; e++) {
        g_base[e] = b;
        g_cursor[e] = b;
        b += g_counts[e];
    }
}

// ---------------- fill compacted assignment lists ----------------
__global__ void fill_kernel() {
    int b = blockIdx.x * blockDim.x + threadIdx.x;
    if (b >= B_TOK) return;
#pragma unroll
    for (int k = 0; k < 2; k++) {
        int e = g_te[b * 2 + k];
        int pos = atomicAdd(&g_cursor[e], 1);
        g_tokmap[pos] = b;
        g_wmap[pos] = g_tw[b * 2 + k];
    }
}

// ================= generic fp32 tiled GEMM: C[M,N] = A[M,K] @ W[K,N] + bias ===
// 64x64 tile, K-tile 16, 256 threads, 4x4 per thread.
template <bool RELU, bool CONCAT>
__global__ __launch_bounds__(256) void gemm_ff(
    const float* __restrict__ A, const float* __restrict__ A2,
    const float* __restrict__ W, const float* __restrict__ bias,
    float* __restrict__ Cmat, int N, int K) {
    __shared__ __align__(16) float As[16][68];
    __shared__ __align__(16) float Bs[16][68];
    int n0 = blockIdx.x * 64, m0 = blockIdx.y * 64;
    int tid = threadIdx.x;
    int ar = tid >> 2, ac = tid & 3;     // A loader: row, k-quad
    int br = tid >> 4, bc = tid & 15;    // W loader: k-row, n-quad
    int tx = tid & 15, ty = tid >> 4;    // compute mapping

    float acc[4][4];
#pragma unroll
    for (int i = 0; i < 4; i++)
#pragma unroll
        for (int j = 0; j < 4; j++) acc[i][j] = 0.f;

    for (int k0 = 0; k0 < K; k0 += 16) {
        int kc = k0 + ac * 4;
        const float* src;
        int lda;
        if (CONCAT) {
            if (kc >= 1024) { src = A2; kc -= 1024; } else src = A;
            lda = 1024;
        } else { src = A; lda = K; }
        float4 av = *(const float4*)&src[(size_t)(m0 + ar) * lda + kc];
        As[ac * 4 + 0][ar] = av.x;
        As[ac * 4 + 1][ar] = av.y;
        As[ac * 4 + 2][ar] = av.z;
        As[ac * 4 + 3][ar] = av.w;
        float4 wv = *(const float4*)&W[(size_t)(k0 + br) * N + n0 + bc * 4];
        *(float4*)&Bs[br][bc * 4] = wv;
        __syncthreads();
#pragma unroll
        for (int k = 0; k < 16; k++) {
            float a[4], b[4];
            *(float4*)a = *(const float4*)&As[k][ty * 4];
            *(float4*)b = *(const float4*)&Bs[k][tx * 4];
#pragma unroll
            for (int i = 0; i < 4; i++)
#pragma unroll
                for (int j = 0; j < 4; j++) acc[i][j] += a[i] * b[j];
        }
        __syncthreads();
    }
#pragma unroll
    for (int i = 0; i < 4; i++) {
        int r = m0 + ty * 4 + i;
#pragma unroll
        for (int j = 0; j < 4; j++) {
            int c = n0 + tx * 4 + j;
            float v = acc[i][j] + bias[c];
            if (RELU) v = fmaxf(v, 0.f);
            Cmat[(size_t)r * N + c] = v;
        }
    }
}

// ================= expert layer-1: hh[slot,1024] = relu(x[tok] @ eW1[e] + eb1[e])
__global__ __launch_bounds__(256) void gemm_e1(const float* __restrict__ eW1,
                                               const float* __restrict__ eb1) {
    __shared__ __align__(16) float As[16][68];
    __shared__ __align__(16) float Bs[16][68];
    int e = blockIdx.z;
    int cnt = g_counts[e];
    int m0 = blockIdx.y * 64;
    if (m0 >= cnt) return;
    int base = g_base[e];
    int n0 = blockIdx.x * 64;
    int tid = threadIdx.x;
    int ar = tid >> 2, ac = tid & 3;
    int br = tid >> 4, bc = tid & 15;
    int tx = tid & 15, ty = tid >> 4;

    int ridx = m0 + ar; if (ridx > cnt - 1) ridx = cnt - 1;
    const float* Arow = g_x + (size_t)g_tokmap[base + ridx] * H;
    const float* W = eW1 + (size_t)e * H * H;

    float acc[4][4];
#pragma unroll
    for (int i = 0; i < 4; i++)
#pragma unroll
        for (int j = 0; j < 4; j++) acc[i][j] = 0.f;

    for (int k0 = 0; k0 < H; k0 += 16) {
        float4 av = *(const float4*)&Arow[k0 + ac * 4];
        As[ac * 4 + 0][ar] = av.x;
        As[ac * 4 + 1][ar] = av.y;
        As[ac * 4 + 2][ar] = av.z;
        As[ac * 4 + 3][ar] = av.w;
        float4 wv = *(const float4*)&W[(size_t)(k0 + br) * H + n0 + bc * 4];
        *(float4*)&Bs[br][bc * 4] = wv;
        __syncthreads();
#pragma unroll
        for (int k = 0; k < 16; k++) {
            float a[4], b[4];
            *(float4*)a = *(const float4*)&As[k][ty * 4];
            *(float4*)b = *(const float4*)&Bs[k][tx * 4];
#pragma unroll
            for (int i = 0; i < 4; i++)
#pragma unroll
                for (int j = 0; j < 4; j++) acc[i][j] += a[i] * b[j];
        }
        __syncthreads();
    }
#pragma unroll
    for (int i = 0; i < 4; i++) {
        int r = ty * 4 + i;
        if (m0 + r < cnt) {
            int slot = base + m0 + r;
#pragma unroll
            for (int j = 0; j < 4; j++) {
                int c = n0 + tx * 4 + j;
                float v = acc[i][j] + eb1[e * H + c];
                g_hh[(size_t)slot * H + c] = fmaxf(v, 0.f);
            }
        }
    }
}

// ================= expert layer-2: routed[tok] += w * (hh[slot] @ eW2[e] + eb2[e])
__global__ __launch_bounds__(256) void gemm_e2(const float* __restrict__ eW2,
                                               const float* __restrict__ eb2) {
    __shared__ __align__(16) float As[16][68];
    __shared__ __align__(16) float Bs[16][68];
    int e = blockIdx.z;
    int cnt = g_counts[e];
    int m0 = blockIdx.y * 64;
    if (m0 >= cnt) return;
    int base = g_base[e];
    int tid = threadIdx.x;
    int ar = tid >> 2, ac = tid & 3;
    int br = tid >> 4, bc = tid & 15;
    int tx = tid & 15, ty = tid >> 4;

    int ridx = m0 + ar; if (ridx > cnt - 1) ridx = cnt - 1;
    const float* Arow = g_hh + (size_t)(base + ridx) * H;
    const float* W = eW2 + (size_t)e * H * P2;

    float acc[4][4];
#pragma unroll
    for (int i = 0; i < 4; i++)
#pragma unroll
        for (int j = 0; j < 4; j++) acc[i][j] = 0.f;

    for (int k0 = 0; k0 < H; k0 += 16) {
        float4 av = *(const float4*)&Arow[k0 + ac * 4];
        As[ac * 4 + 0][ar] = av.x;
        As[ac * 4 + 1][ar] = av.y;
        As[ac * 4 + 2][ar] = av.z;
        As[ac * 4 + 3][ar] = av.w;
        float4 wv = *(const float4*)&W[(size_t)(k0 + br) * P2 + bc * 4];
        *(float4*)&Bs[br][bc * 4] = wv;
        __syncthreads();
#pragma unroll
        for (int k = 0; k < 16; k++) {
            float a[4], b[4];
            *(float4*)a = *(const float4*)&As[k][ty * 4];
            *(float4*)b = *(const float4*)&Bs[k][tx * 4];
#pragma unroll
            for (int i = 0; i < 4; i++)
#pragma unroll
                for (int j = 0; j < 4; j++) acc[i][j] += a[i] * b[j];
        }
        __syncthreads();
    }
#pragma unroll
    for (int i = 0; i < 4; i++) {
        int r = ty * 4 + i;
        if (m0 + r < cnt) {
            int slot = base + m0 + r;
            int tok = g_tokmap[slot];
            float w = g_wmap[slot];
#pragma unroll
            for (int j = 0; j < 4; j++) {
                int c = tx * 4 + j;
                float v = acc[i][j] + eb2[e * P2 + c];
                atomicAdd(&g_routed[(size_t)tok * P2 + c], w * v);
            }
        }
    }
}

// ---------------- final gate + sigmoid (warp per token) ----------------
__global__ __launch_bounds__(256) void gate_kernel(const float* __restrict__ gW,
                                                   const float* __restrict__ gb,
                                                   float* __restrict__ out) {
    __shared__ __align__(16) float sW[128 * 64];  // 32KB
    for (int i = threadIdx.x; i < 128 * 64 / 4; i += 256)
        *(float4*)&sW[i * 4] = *(const float4*)&gW[i * 4];
    __syncthreads();
    int warp = threadIdx.x >> 5;
    int lane = threadIdx.x & 31;
    int tok = blockIdx.x * 8 + warp;
    if (tok >= B_TOK) return;
    const float* r = g_routed + (size_t)tok * P2;
    const float* s = g_sharedout + (size_t)tok * P2;
    float a0 = gb[lane], a1 = gb[lane + 32];
#pragma unroll 8
    for (int k = 0; k < 64; k++) {
        float c = r[k];
        a0 += c * sW[k * 64 + lane];
        a1 += c * sW[k * 64 + lane + 32];
    }
#pragma unroll 8
    for (int k = 0; k < 64; k++) {
        float c = s[k];
        a0 += c * sW[(64 + k) * 64 + lane];
        a1 += c * sW[(64 + k) * 64 + lane + 32];
    }
    out[(size_t)tok * P2 + lane]      = 1.0f / (1.0f + expf(-a0));
    out[(size_t)tok * P2 + lane + 32] = 1.0f / (1.0f + expf(-a1));
}

// ---------------- host launch sequence ----------------
extern "C" void kernel_launch(void* const* d_in, const int* in_sizes, int n_in,
                              void* d_out, int out_size) {
    const float* mm   = (const float*)d_in[0];
    const float* qf   = (const float*)d_in[1];
    const float* lng  = (const float*)d_in[2];
    const float* lnb  = (const float*)d_in[3];
    const float* pe   = (const float*)d_in[4];
    const float* qW   = (const float*)d_in[5];
    const float* qb   = (const float*)d_in[6];
    const float* eW1  = (const float*)d_in[7];
    const float* eb1  = (const float*)d_in[8];
    const float* eW2  = (const float*)d_in[9];
    const float* eb2  = (const float*)d_in[10];
    const float* sW1  = (const float*)d_in[11];
    const float* sb1  = (const float*)d_in[12];
    const float* sW2  = (const float*)d_in[13];
    const float* sb2  = (const float*)d_in[14];
    const float* gW   = (const float*)d_in[15];
    const float* gb   = (const float*)d_in[16];
    float* out = (float*)d_out;

    float *p_x, *p_q, *p_sh, *p_so;
    cudaGetSymbolAddress((void**)&p_x,  g_x);
    cudaGetSymbolAddress((void**)&p_q,  g_q);
    cudaGetSymbolAddress((void**)&p_sh, g_sh);
    cudaGetSymbolAddress((void**)&p_so, g_sharedout);

    reset_kernel<<<4096, 256>>>();
    ln_kernel<<<B_TOK / 8, 256>>>(mm, lng, lnb);
    pilot_norm_kernel<<<1, 1024>>>(pe);

    // qproj: [B,2048] @ [2048,1024] + b  (A = concat(x, query))
    gemm_ff<false, true><<<dim3(16, 256), 256>>>(p_x, qf, qW, qb, p_q, 1024, 2048);
    l2q_kernel<<<B_TOK / 8, 256>>>();
    router_kernel<<<B_TOK / 8, 256>>>();
    scan_kernel<<<1, 1>>>();
    fill_kernel<<<B_TOK / 256, 256>>>();

    // routed experts (sparse, per-expert segments)
    gemm_e1<<<dim3(16, B_TOK / 64, NE), 256>>>(eW1, eb1);
    gemm_e2<<<dim3(1, B_TOK / 64, NE), 256>>>(eW2, eb2);

    // shared expert
    gemm_ff<true, false><<<dim3(16, 256), 256>>>(p_x, nullptr, sW1, sb1, p_sh, 1024, 1024);
    gemm_ff<false, false><<<dim3(1, 256), 256>>>(p_sh, nullptr, sW2, sb2, p_so, 64, 1024);

    // gate + sigmoid -> output
    gate_kernel<<<B_TOK / 8, 256>>>(gW, gb, out);
}

// round 14
// speedup vs baseline: 1.0021x; 1.0021x over previous
#include <cuda_runtime.h>
#include <math.h>

// ---------------- problem constants ----------------
#define B_TOK 16384
#define H     1024
#define P2    64      // 2P
#define NE    8
#define EC    32      // E*C pilots
#define NSLOT (2*B_TOK)

// ---------------- device scratch (static; no allocations allowed) ----------------
__device__ float g_x[B_TOK * H];          // layernorm output
__device__ float g_q[B_TOK * H];          // qproj output, then l2-normalized in place
__device__ float g_pn[EC * H];            // normalized pilots
__device__ int   g_te[B_TOK * 2];         // top-2 expert ids per token
__device__ float g_tw[B_TOK * 2];         // top-2 weights per token
__device__ int   g_counts[NE];
__device__ int   g_base[NE];
__device__ int   g_cursor[NE];
__device__ int   g_tokmap[NSLOT];
__device__ float g_wmap[NSLOT];
__device__ float g_hh[(NSLOT + 64) * H];  // expert layer-1 activations (post-relu)
__device__ float g_sh[B_TOK * H];         // shared expert layer-1 activations
__device__ float g_routed[B_TOK * P2];
__device__ float g_sharedout[B_TOK * P2];

// ---------------- reset ----------------
__global__ void reset_kernel() {
    int idx = blockIdx.x * blockDim.x + threadIdx.x;
    if (idx < B_TOK * P2) g_routed[idx] = 0.0f;
    if (idx < NE) g_counts[idx] = 0;
}

// ---------------- layernorm (warp per row) ----------------
__global__ void ln_kernel(const float* __restrict__ mm,
                          const float* __restrict__ gamma,
                          const float* __restrict__ beta) {
    int warp = (blockIdx.x * blockDim.x + threadIdx.x) >> 5;
    int lane = threadIdx.x & 31;
    if (warp >= B_TOK) return;
    const float* row = mm + (size_t)warp * H;
    float s = 0.f, s2 = 0.f;
    for (int i = lane; i < H; i += 32) { float v = row[i]; s += v; s2 += v * v; }
    for (int o = 16; o; o >>= 1) {
        s  += __shfl_xor_sync(0xffffffff, s, o);
        s2 += __shfl_xor_sync(0xffffffff, s2, o);
    }
    float mean = s * (1.0f / H);
    float var  = s2 * (1.0f / H) - mean * mean;
    float inv  = rsqrtf(var + 1e-5f);
    float* out = g_x + (size_t)warp * H;
    for (int i = lane; i < H; i += 32)
        out[i] = (row[i] - mean) * inv * gamma[i] + beta[i];
}

// ---------------- pilot l2 normalize (warp per pilot, 32 pilots) ----------------
__global__ void pilot_norm_kernel(const float* __restrict__ pe) {
    int warp = threadIdx.x >> 5;
    int lane = threadIdx.x & 31;
    const float* row = pe + (size_t)warp * H;
    float s2 = 0.f;
    for (int i = lane; i < H; i += 32) { float v = row[i]; s2 += v * v; }
    for (int o = 16; o; o >>= 1) s2 += __shfl_xor_sync(0xffffffff, s2, o);
    float inv = 1.0f / fmaxf(sqrtf(s2), 1e-12f);
    for (int i = lane; i < H; i += 32) g_pn[warp * H + i] = row[i] * inv;
}

// ---------------- l2 normalize q rows in place (warp per row) ----------------
__global__ void l2q_kernel() {
    int warp = (blockIdx.x * blockDim.x + threadIdx.x) >> 5;
    int lane = threadIdx.x & 31;
    if (warp >= B_TOK) return;
    float* row = g_q + (size_t)warp * H;
    float s2 = 0.f;
    for (int i = lane; i < H; i += 32) { float v = row[i]; s2 += v * v; }
    for (int o = 16; o; o >>= 1) s2 += __shfl_xor_sync(0xffffffff, s2, o);
    float inv = 1.0f / fmaxf(sqrtf(s2), 1e-12f);
    for (int i = lane; i < H; i += 32) row[i] *= inv;
}

// ---------------- router: sims, softmax/temp, top2, counts (warp per token) ---
__global__ void router_kernel() {
    int warp = (blockIdx.x * blockDim.x + threadIdx.x) >> 5;
    int lane = threadIdx.x & 31;
    if (warp >= B_TOK) return;
    const float* q = g_q + (size_t)warp * H;

    float acc[EC];
#pragma unroll
    for (int ec = 0; ec < EC; ec++) acc[ec] = 0.f;

    for (int h = lane; h < H; h += 32) {
        float qv = q[h];
#pragma unroll
        for (int ec = 0; ec < EC; ec++) acc[ec] += qv * g_pn[ec * H + h];
    }

    float sc[NE];
#pragma unroll
    for (int e = 0; e < NE; e++) sc[e] = 0.f;
#pragma unroll
    for (int ec = 0; ec < EC; ec++) {
        float v = acc[ec];
        for (int o = 16; o; o >>= 1) v += __shfl_xor_sync(0xffffffff, v, o);
        sc[ec >> 2] += v * 0.25f;
    }

    // softmax(scores / 0.1)
    float m = -1e30f;
#pragma unroll
    for (int e = 0; e < NE; e++) m = fmaxf(m, sc[e]);
    float p[NE], sum = 0.f;
#pragma unroll
    for (int e = 0; e < NE; e++) { p[e] = expf((sc[e] - m) * 10.f); sum += p[e]; }

    // top-2 on scores (monotone with probs); strict > => lowest index wins ties (jax semantics)
    int i1 = 0;
#pragma unroll
    for (int e = 1; e < NE; e++) if (sc[e] > sc[i1]) i1 = e;
    int i2 = (i1 == 0) ? 1 : 0;
#pragma unroll
    for (int e = 0; e < NE; e++) if (e != i1 && sc[e] > sc[i2]) i2 = e;

    float w1 = p[i1] / sum, w2 = p[i2] / sum;
    float d = w1 + w2 + 1e-6f;
    w1 /= d; w2 /= d;

    if (lane == 0) {
        g_te[warp * 2 + 0] = i1; g_te[warp * 2 + 1] = i2;
        g_tw[warp * 2 + 0] = w1; g_tw[warp * 2 + 1] = w2;
        atomicAdd(&g_counts[i1], 1);
        atomicAdd(&g_counts[i2], 1);
    }
}

// ---------------- scan over 8 experts ----------------
__global__ void scan_kernel() {
    int b = 0;
    for (int e = 0; e < NE; e++) {
        g_base[e] = b;
        g_cursor[e] = b;
        b += g_counts[e];
    }
}

// ---------------- fill compacted assignment lists ----------------
__global__ void fill_kernel() {
    int b = blockIdx.x * blockDim.x + threadIdx.x;
    if (b >= B_TOK) return;
#pragma unroll
    for (int k = 0; k < 2; k++) {
        int e = g_te[b * 2 + k];
        int pos = atomicAdd(&g_cursor[e], 1);
        g_tokmap[pos] = b;
        g_wmap[pos] = g_tw[b * 2 + k];
    }
}

// ================= generic fp32 tiled GEMM: C[M,N] = A[M,K] @ W[K,N] + bias ===
// 64x64 tile, K-tile 16, 256 threads, 4x4 per thread.
template <bool RELU, bool CONCAT>
__global__ __launch_bounds__(256) void gemm_ff(
    const float* __restrict__ A, const float* __restrict__ A2,
    const float* __restrict__ W, const float* __restrict__ bias,
    float* __restrict__ Cmat, int N, int K) {
    __shared__ __align__(16) float As[16][68];
    __shared__ __align__(16) float Bs[16][68];
    int n0 = blockIdx.x * 64, m0 = blockIdx.y * 64;
    int tid = threadIdx.x;
    int ar = tid >> 2, ac = tid & 3;     // A loader: row, k-quad
    int br = tid >> 4, bc = tid & 15;    // W loader: k-row, n-quad
    int tx = tid & 15, ty = tid >> 4;    // compute mapping

    float acc[4][4];
#pragma unroll
    for (int i = 0; i < 4; i++)
#pragma unroll
        for (int j = 0; j < 4; j++) acc[i][j] = 0.f;

    for (int k0 = 0; k0 < K; k0 += 16) {
        int kc = k0 + ac * 4;
        const float* src;
        int lda;
        if (CONCAT) {
            if (kc >= 1024) { src = A2; kc -= 1024; } else src = A;
            lda = 1024;
        } else { src = A; lda = K; }
        float4 av = *(const float4*)&src[(size_t)(m0 + ar) * lda + kc];
        As[ac * 4 + 0][ar] = av.x;
        As[ac * 4 + 1][ar] = av.y;
        As[ac * 4 + 2][ar] = av.z;
        As[ac * 4 + 3][ar] = av.w;
        float4 wv = *(const float4*)&W[(size_t)(k0 + br) * N + n0 + bc * 4];
        *(float4*)&Bs[br][bc * 4] = wv;
        __syncthreads();
#pragma unroll
        for (int k = 0; k < 16; k++) {
            float a[4], b[4];
            *(float4*)a = *(const float4*)&As[k][ty * 4];
            *(float4*)b = *(const float4*)&Bs[k][tx * 4];
#pragma unroll
            for (int i = 0; i < 4; i++)
#pragma unroll
                for (int j = 0; j < 4; j++) acc[i][j] += a[i] * b[j];
        }
        __syncthreads();
    }
#pragma unroll
    for (int i = 0; i < 4; i++) {
        int r = m0 + ty * 4 + i;
#pragma unroll
        for (int j = 0; j < 4; j++) {
            int c = n0 + tx * 4 + j;
            float v = acc[i][j] + bias[c];
            if (RELU) v = fmaxf(v, 0.f);
            Cmat[(size_t)r * N + c] = v;
        }
    }
}

// ================= expert layer-1: hh[slot,1024] = relu(x[tok] @ eW1[e] + eb1[e])
__global__ __launch_bounds__(256) void gemm_e1(const float* __restrict__ eW1,
                                               const float* __restrict__ eb1) {
    __shared__ __align__(16) float As[16][68];
    __shared__ __align__(16) float Bs[16][68];
    int e = blockIdx.z;
    int cnt = g_counts[e];
    int m0 = blockIdx.y * 64;
    if (m0 >= cnt) return;
    int base = g_base[e];
    int n0 = blockIdx.x * 64;
    int tid = threadIdx.x;
    int ar = tid >> 2, ac = tid & 3;
    int br = tid >> 4, bc = tid & 15;
    int tx = tid & 15, ty = tid >> 4;

    int ridx = m0 + ar; if (ridx > cnt - 1) ridx = cnt - 1;
    const float* Arow = g_x + (size_t)g_tokmap[base + ridx] * H;
    const float* W = eW1 + (size_t)e * H * H;

    float acc[4][4];
#pragma unroll
    for (int i = 0; i < 4; i++)
#pragma unroll
        for (int j = 0; j < 4; j++) acc[i][j] = 0.f;

    for (int k0 = 0; k0 < H; k0 += 16) {
        float4 av = *(const float4*)&Arow[k0 + ac * 4];
        As[ac * 4 + 0][ar] = av.x;
        As[ac * 4 + 1][ar] = av.y;
        As[ac * 4 + 2][ar] = av.z;
        As[ac * 4 + 3][ar] = av.w;
        float4 wv = *(const float4*)&W[(size_t)(k0 + br) * H + n0 + bc * 4];
        *(float4*)&Bs[br][bc * 4] = wv;
        __syncthreads();
#pragma unroll
        for (int k = 0; k < 16; k++) {
            float a[4], b[4];
            *(float4*)a = *(const float4*)&As[k][ty * 4];
            *(float4*)b = *(const float4*)&Bs[k][tx * 4];
#pragma unroll
            for (int i = 0; i < 4; i++)
#pragma unroll
                for (int j = 0; j < 4; j++) acc[i][j] += a[i] * b[j];
        }
        __syncthreads();
    }
#pragma unroll
    for (int i = 0; i < 4; i++) {
        int r = ty * 4 + i;
        if (m0 + r < cnt) {
            int slot = base + m0 + r;
#pragma unroll
            for (int j = 0; j < 4; j++) {
                int c = n0 + tx * 4 + j;
                float v = acc[i][j] + eb1[e * H + c];
                g_hh[(size_t)slot * H + c] = fmaxf(v, 0.f);
            }
        }
    }
}

// ================= expert layer-2: routed[tok] += w * (hh[slot] @ eW2[e] + eb2[e])
__global__ __launch_bounds__(256) void gemm_e2(const float* __restrict__ eW2,
                                               const float* __restrict__ eb2) {
    __shared__ __align__(16) float As[16][68];
    __shared__ __align__(16) float Bs[16][68];
    int e = blockIdx.z;
    int cnt = g_counts[e];
    int m0 = blockIdx.y * 64;
    if (m0 >= cnt) return;
    int base = g_base[e];
    int tid = threadIdx.x;
    int ar = tid >> 2, ac = tid & 3;
    int br = tid >> 4, bc = tid & 15;
    int tx = tid & 15, ty = tid >> 4;

    int ridx = m0 + ar; if (ridx > cnt - 1) ridx = cnt - 1;
    const float* Arow = g_hh + (size_t)(base + ridx) * H;
    const float* W = eW2 + (size_t)e * H * P2;

    float acc[4][4];
#pragma unroll
    for (int i = 0; i < 4; i++)
#pragma unroll
        for (int j = 0; j < 4; j++) acc[i][j] = 0.f;

    for (int k0 = 0; k0 < H; k0 += 16) {
        float4 av = *(const float4*)&Arow[k0 + ac * 4];
        As[ac * 4 + 0][ar] = av.x;
        As[ac * 4 + 1][ar] = av.y;
        As[ac * 4 + 2][ar] = av.z;
        As[ac * 4 + 3][ar] = av.w;
        float4 wv = *(const float4*)&W[(size_t)(k0 + br) * P2 + bc * 4];
        *(float4*)&Bs[br][bc * 4] = wv;
        __syncthreads();
#pragma unroll
        for (int k = 0; k < 16; k++) {
            float a[4], b[4];
            *(float4*)a = *(const float4*)&As[k][ty * 4];
            *(float4*)b = *(const float4*)&Bs[k][tx * 4];
#pragma unroll
            for (int i = 0; i < 4; i++)
#pragma unroll
                for (int j = 0; j < 4; j++) acc[i][j] += a[i] * b[j];
        }
        __syncthreads();
    }
#pragma unroll
    for (int i = 0; i < 4; i++) {
        int r = ty * 4 + i;
        if (m0 + r < cnt) {
            int slot = base + m0 + r;
            int tok = g_tokmap[slot];
            float w = g_wmap[slot];
#pragma unroll
            for (int j = 0; j < 4; j++) {
                int c = tx * 4 + j;
                float v = acc[i][j] + eb2[e * P2 + c];
                atomicAdd(&g_routed[(size_t)tok * P2 + c], w * v);
            }
        }
    }
}

// ---------------- final gate + sigmoid (warp per token) ----------------
__global__ __launch_bounds__(256) void gate_kernel(const float* __restrict__ gW,
                                                   const float* __restrict__ gb,
                                                   float* __restrict__ out) {
    __shared__ __align__(16) float sW[128 * 64];  // 32KB
    for (int i = threadIdx.x; i < 128 * 64 / 4; i += 256)
        *(float4*)&sW[i * 4] = *(const float4*)&gW[i * 4];
    __syncthreads();
    int warp = threadIdx.x >> 5;
    int lane = threadIdx.x & 31;
    int tok = blockIdx.x * 8 + warp;
    if (tok >= B_TOK) return;
    const float* r = g_routed + (size_t)tok * P2;
    const float* s = g_sharedout + (size_t)tok * P2;
    float a0 = gb[lane], a1 = gb[lane + 32];
#pragma unroll 8
    for (int k = 0; k < 64; k++) {
        float c = r[k];
        a0 += c * sW[k * 64 + lane];
        a1 += c * sW[k * 64 + lane + 32];
    }
#pragma unroll 8
    for (int k = 0; k < 64; k++) {
        float c = s[k];
        a0 += c * sW[(64 + k) * 64 + lane];
        a1 += c * sW[(64 + k) * 64 + lane + 32];
    }
    out[(size_t)tok * P2 + lane]      = 1.0f / (1.0f + expf(-a0));
    out[(size_t)tok * P2 + lane + 32] = 1.0f / (1.0f + expf(-a1));
}

// ---------------- host launch sequence ----------------
extern "C" void kernel_launch(void* const* d_in, const int* in_sizes, int n_in,
                              void* d_out, int out_size) {
    const float* mm   = (const float*)d_in[0];
    const float* qf   = (const float*)d_in[1];
    const float* lng  = (const float*)d_in[2];
    const float* lnb  = (const float*)d_in[3];
    const float* pe   = (const float*)d_in[4];
    const float* qW   = (const float*)d_in[5];
    const float* qb   = (const float*)d_in[6];
    const float* eW1  = (const float*)d_in[7];
    const float* eb1  = (const float*)d_in[8];
    const float* eW2  = (const float*)d_in[9];
    const float* eb2  = (const float*)d_in[10];
    const float* sW1  = (const float*)d_in[11];
    const float* sb1  = (const float*)d_in[12];
    const float* sW2  = (const float*)d_in[13];
    const float* sb2  = (const float*)d_in[14];
    const float* gW   = (const float*)d_in[15];
    const float* gb   = (const float*)d_in[16];
    float* out = (float*)d_out;

    float *p_x, *p_q, *p_sh, *p_so;
    cudaGetSymbolAddress((void**)&p_x,  g_x);
    cudaGetSymbolAddress((void**)&p_q,  g_q);
    cudaGetSymbolAddress((void**)&p_sh, g_sh);
    cudaGetSymbolAddress((void**)&p_so, g_sharedout);

    reset_kernel<<<4096, 256>>>();
    ln_kernel<<<B_TOK / 8, 256>>>(mm, lng, lnb);
    pilot_norm_kernel<<<1, 1024>>>(pe);

    // qproj: [B,2048] @ [2048,1024] + b  (A = concat(x, query))
    gemm_ff<false, true><<<dim3(16, 256), 256>>>(p_x, qf, qW, qb, p_q, 1024, 2048);
    l2q_kernel<<<B_TOK / 8, 256>>>();
    router_kernel<<<B_TOK / 8, 256>>>();
    scan_kernel<<<1, 1>>>();
    fill_kernel<<<B_TOK / 256, 256>>>();

    // routed experts (sparse, per-expert segments)
    gemm_e1<<<dim3(16, B_TOK / 64, NE), 256>>>(eW1, eb1);
    gemm_e2<<<dim3(1, B_TOK / 64, NE), 256>>>(eW2, eb2);

    // shared expert
    gemm_ff<true, false><<<dim3(16, 256), 256>>>(p_x, nullptr, sW1, sb1, p_sh, 1024, 1024);
    gemm_ff<false, false><<<dim3(1, 256), 256>>>(p_sh, nullptr, sW2, sb2, p_so, 64, 1024);

    // gate + sigmoid -> output
    gate_kernel<<<B_TOK / 8, 256>>>(gW, gb, out);
}

// round 15
// speedup vs baseline: 1.0031x; 1.0010x over previous
#include <cuda_runtime.h>
#include <math.h>

// ---------------- problem constants ----------------
#define B_TOK 16384
#define H     1024
#define P2    64      // 2P
#define NE    8
#define EC    32      // E*C pilots
#define NSLOT (2*B_TOK)

// ---------------- device scratch (static; no allocations allowed) ----------------
__device__ float g_x[B_TOK * H];          // layernorm output
__device__ float g_q[B_TOK * H];          // qproj output, then l2-normalized in place
__device__ float g_pn[EC * H];            // normalized pilots
__device__ int   g_te[B_TOK * 2];         // top-2 expert ids per token
__device__ float g_tw[B_TOK * 2];         // top-2 weights per token
__device__ int   g_counts[NE];
__device__ int   g_base[NE];
__device__ int   g_cursor[NE];
__device__ int   g_tokmap[NSLOT];
__device__ float g_wmap[NSLOT];
__device__ float g_hh[(NSLOT + 64) * H];  // expert layer-1 activations (post-relu)
__device__ float g_sh[B_TOK * H];         // shared expert layer-1 activations
__device__ float g_routed[B_TOK * P2];
__device__ float g_sharedout[B_TOK * P2];

// ---------------- reset ----------------
__global__ void reset_kernel() {
    int idx = blockIdx.x * blockDim.x + threadIdx.x;
    if (idx < B_TOK * P2) g_routed[idx] = 0.0f;
    if (idx < NE) g_counts[idx] = 0;
}

// ---------------- layernorm (warp per row) ----------------
__global__ void ln_kernel(const float* __restrict__ mm,
                          const float* __restrict__ gamma,
                          const float* __restrict__ beta) {
    int warp = (blockIdx.x * blockDim.x + threadIdx.x) >> 5;
    int lane = threadIdx.x & 31;
    if (warp >= B_TOK) return;
    const float* row = mm + (size_t)warp * H;
    float s = 0.f, s2 = 0.f;
    for (int i = lane; i < H; i += 32) { float v = row[i]; s += v; s2 += v * v; }
    for (int o = 16; o; o >>= 1) {
        s  += __shfl_xor_sync(0xffffffff, s, o);
        s2 += __shfl_xor_sync(0xffffffff, s2, o);
    }
    float mean = s * (1.0f / H);
    float var  = s2 * (1.0f / H) - mean * mean;
    float inv  = rsqrtf(var + 1e-5f);
    float* out = g_x + (size_t)warp * H;
    for (int i = lane; i < H; i += 32)
        out[i] = (row[i] - mean) * inv * gamma[i] + beta[i];
}

// ---------------- pilot l2 normalize (warp per pilot, 32 pilots) ----------------
__global__ void pilot_norm_kernel(const float* __restrict__ pe) {
    int warp = threadIdx.x >> 5;
    int lane = threadIdx.x & 31;
    const float* row = pe + (size_t)warp * H;
    float s2 = 0.f;
    for (int i = lane; i < H; i += 32) { float v = row[i]; s2 += v * v; }
    for (int o = 16; o; o >>= 1) s2 += __shfl_xor_sync(0xffffffff, s2, o);
    float inv = 1.0f / fmaxf(sqrtf(s2), 1e-12f);
    for (int i = lane; i < H; i += 32) g_pn[warp * H + i] = row[i] * inv;
}

// ---------------- l2 normalize q rows in place (warp per row) ----------------
__global__ void l2q_kernel() {
    int warp = (blockIdx.x * blockDim.x + threadIdx.x) >> 5;
    int lane = threadIdx.x & 31;
    if (warp >= B_TOK) return;
    float* row = g_q + (size_t)warp * H;
    float s2 = 0.f;
    for (int i = lane; i < H; i += 32) { float v = row[i]; s2 += v * v; }
    for (int o = 16; o; o >>= 1) s2 += __shfl_xor_sync(0xffffffff, s2, o);
    float inv = 1.0f / fmaxf(sqrtf(s2), 1e-12f);
    for (int i = lane; i < H; i += 32) row[i] *= inv;
}

// ---------------- router: sims, softmax/temp, top2, counts (warp per token) ---
__global__ void router_kernel() {
    int warp = (blockIdx.x * blockDim.x + threadIdx.x) >> 5;
    int lane = threadIdx.x & 31;
    if (warp >= B_TOK) return;
    const float* q = g_q + (size_t)warp * H;

    float acc[EC];
#pragma unroll
    for (int ec = 0; ec < EC; ec++) acc[ec] = 0.f;

    for (int h = lane; h < H; h += 32) {
        float qv = q[h];
#pragma unroll
        for (int ec = 0; ec < EC; ec++) acc[ec] += qv * g_pn[ec * H + h];
    }

    float sc[NE];
#pragma unroll
    for (int e = 0; e < NE; e++) sc[e] = 0.f;
#pragma unroll
    for (int ec = 0; ec < EC; ec++) {
        float v = acc[ec];
        for (int o = 16; o; o >>= 1) v += __shfl_xor_sync(0xffffffff, v, o);
        sc[ec >> 2] += v * 0.25f;
    }

    // softmax(scores / 0.1)
    float m = -1e30f;
#pragma unroll
    for (int e = 0; e < NE; e++) m = fmaxf(m, sc[e]);
    float p[NE], sum = 0.f;
#pragma unroll
    for (int e = 0; e < NE; e++) { p[e] = expf((sc[e] - m) * 10.f); sum += p[e]; }

    // top-2 on scores (monotone with probs); strict > => lowest index wins ties (jax semantics)
    int i1 = 0;
#pragma unroll
    for (int e = 1; e < NE; e++) if (sc[e] > sc[i1]) i1 = e;
    int i2 = (i1 == 0) ? 1 : 0;
#pragma unroll
    for (int e = 0; e < NE; e++) if (e != i1 && sc[e] > sc[i2]) i2 = e;

    float w1 = p[i1] / sum, w2 = p[i2] / sum;
    float d = w1 + w2 + 1e-6f;
    w1 /= d; w2 /= d;

    if (lane == 0) {
        g_te[warp * 2 + 0] = i1; g_te[warp * 2 + 1] = i2;
        g_tw[warp * 2 + 0] = w1; g_tw[warp * 2 + 1] = w2;
        atomicAdd(&g_counts[i1], 1);
        atomicAdd(&g_counts[i2], 1);
    }
}

// ---------------- scan over 8 experts ----------------
__global__ void scan_kernel() {
    int b = 0;
    for (int e = 0; e < NE; e++) {
        g_base[e] = b;
        g_cursor[e] = b;
        b += g_counts[e];
    }
}

// ---------------- fill compacted assignment lists ----------------
__global__ void fill_kernel() {
    int b = blockIdx.x * blockDim.x + threadIdx.x;
    if (b >= B_TOK) return;
#pragma unroll
    for (int k = 0; k < 2; k++) {
        int e = g_te[b * 2 + k];
        int pos = atomicAdd(&g_cursor[e], 1);
        g_tokmap[pos] = b;
        g_wmap[pos] = g_tw[b * 2 + k];
    }
}

// ================= generic fp32 tiled GEMM: C[M,N] = A[M,K] @ W[K,N] + bias ===
// 64x64 tile, K-tile 16, 256 threads, 4x4 per thread.
template <bool RELU, bool CONCAT>
__global__ __launch_bounds__(256) void gemm_ff(
    const float* __restrict__ A, const float* __restrict__ A2,
    const float* __restrict__ W, const float* __restrict__ bias,
    float* __restrict__ Cmat, int N, int K) {
    __shared__ __align__(16) float As[16][68];
    __shared__ __align__(16) float Bs[16][68];
    int n0 = blockIdx.x * 64, m0 = blockIdx.y * 64;
    int tid = threadIdx.x;
    int ar = tid >> 2, ac = tid & 3;     // A loader: row, k-quad
    int br = tid >> 4, bc = tid & 15;    // W loader: k-row, n-quad
    int tx = tid & 15, ty = tid >> 4;    // compute mapping

    float acc[4][4];
#pragma unroll
    for (int i = 0; i < 4; i++)
#pragma unroll
        for (int j = 0; j < 4; j++) acc[i][j] = 0.f;

    for (int k0 = 0; k0 < K; k0 += 16) {
        int kc = k0 + ac * 4;
        const float* src;
        int lda;
        if (CONCAT) {
            if (kc >= 1024) { src = A2; kc -= 1024; } else src = A;
            lda = 1024;
        } else { src = A; lda = K; }
        float4 av = *(const float4*)&src[(size_t)(m0 + ar) * lda + kc];
        As[ac * 4 + 0][ar] = av.x;
        As[ac * 4 + 1][ar] = av.y;
        As[ac * 4 + 2][ar] = av.z;
        As[ac * 4 + 3][ar] = av.w;
        float4 wv = *(const float4*)&W[(size_t)(k0 + br) * N + n0 + bc * 4];
        *(float4*)&Bs[br][bc * 4] = wv;
        __syncthreads();
#pragma unroll
        for (int k = 0; k < 16; k++) {
            float a[4], b[4];
            *(float4*)a = *(const float4*)&As[k][ty * 4];
            *(float4*)b = *(const float4*)&Bs[k][tx * 4];
#pragma unroll
            for (int i = 0; i < 4; i++)
#pragma unroll
                for (int j = 0; j < 4; j++) acc[i][j] += a[i] * b[j];
        }
        __syncthreads();
    }
#pragma unroll
    for (int i = 0; i < 4; i++) {
        int r = m0 + ty * 4 + i;
#pragma unroll
        for (int j = 0; j < 4; j++) {
            int c = n0 + tx * 4 + j;
            float v = acc[i][j] + bias[c];
            if (RELU) v = fmaxf(v, 0.f);
            Cmat[(size_t)r * N + c] = v;
        }
    }
}

// ================= expert layer-1: hh[slot,1024] = relu(x[tok] @ eW1[e] + eb1[e])
__global__ __launch_bounds__(256) void gemm_e1(const float* __restrict__ eW1,
                                               const float* __restrict__ eb1) {
    __shared__ __align__(16) float As[16][68];
    __shared__ __align__(16) float Bs[16][68];
    int e = blockIdx.z;
    int cnt = g_counts[e];
    int m0 = blockIdx.y * 64;
    if (m0 >= cnt) return;
    int base = g_base[e];
    int n0 = blockIdx.x * 64;
    int tid = threadIdx.x;
    int ar = tid >> 2, ac = tid & 3;
    int br = tid >> 4, bc = tid & 15;
    int tx = tid & 15, ty = tid >> 4;

    int ridx = m0 + ar; if (ridx > cnt - 1) ridx = cnt - 1;
    const float* Arow = g_x + (size_t)g_tokmap[base + ridx] * H;
    const float* W = eW1 + (size_t)e * H * H;

    float acc[4][4];
#pragma unroll
    for (int i = 0; i < 4; i++)
#pragma unroll
        for (int j = 0; j < 4; j++) acc[i][j] = 0.f;

    for (int k0 = 0; k0 < H; k0 += 16) {
        float4 av = *(const float4*)&Arow[k0 + ac * 4];
        As[ac * 4 + 0][ar] = av.x;
        As[ac * 4 + 1][ar] = av.y;
        As[ac * 4 + 2][ar] = av.z;
        As[ac * 4 + 3][ar] = av.w;
        float4 wv = *(const float4*)&W[(size_t)(k0 + br) * H + n0 + bc * 4];
        *(float4*)&Bs[br][bc * 4] = wv;
        __syncthreads();
#pragma unroll
        for (int k = 0; k < 16; k++) {
            float a[4], b[4];
            *(float4*)a = *(const float4*)&As[k][ty * 4];
            *(float4*)b = *(const float4*)&Bs[k][tx * 4];
#pragma unroll
            for (int i = 0; i < 4; i++)
#pragma unroll
                for (int j = 0; j < 4; j++) acc[i][j] += a[i] * b[j];
        }
        __syncthreads();
    }
#pragma unroll
    for (int i = 0; i < 4; i++) {
        int r = ty * 4 + i;
        if (m0 + r < cnt) {
            int slot = base + m0 + r;
#pragma unroll
            for (int j = 0; j < 4; j++) {
                int c = n0 + tx * 4 + j;
                float v = acc[i][j] + eb1[e * H + c];
                g_hh[(size_t)slot * H + c] = fmaxf(v, 0.f);
            }
        }
    }
}

// ================= expert layer-2: routed[tok] += w * (hh[slot] @ eW2[e] + eb2[e])
__global__ __launch_bounds__(256) void gemm_e2(const float* __restrict__ eW2,
                                               const float* __restrict__ eb2) {
    __shared__ __align__(16) float As[16][68];
    __shared__ __align__(16) float Bs[16][68];
    int e = blockIdx.z;
    int cnt = g_counts[e];
    int m0 = blockIdx.y * 64;
    if (m0 >= cnt) return;
    int base = g_base[e];
    int tid = threadIdx.x;
    int ar = tid >> 2, ac = tid & 3;
    int br = tid >> 4, bc = tid & 15;
    int tx = tid & 15, ty = tid >> 4;

    int ridx = m0 + ar; if (ridx > cnt - 1) ridx = cnt - 1;
    const float* Arow = g_hh + (size_t)(base + ridx) * H;
    const float* W = eW2 + (size_t)e * H * P2;

    float acc[4][4];
#pragma unroll
    for (int i = 0; i < 4; i++)
#pragma unroll
        for (int j = 0; j < 4; j++) acc[i][j] = 0.f;

    for (int k0 = 0; k0 < H; k0 += 16) {
        float4 av = *(const float4*)&Arow[k0 + ac * 4];
        As[ac * 4 + 0][ar] = av.x;
        As[ac * 4 + 1][ar] = av.y;
        As[ac * 4 + 2][ar] = av.z;
        As[ac * 4 + 3][ar] = av.w;
        float4 wv = *(const float4*)&W[(size_t)(k0 + br) * P2 + bc * 4];
        *(float4*)&Bs[br][bc * 4] = wv;
        __syncthreads();
#pragma unroll
        for (int k = 0; k < 16; k++) {
            float a[4], b[4];
            *(float4*)a = *(const float4*)&As[k][ty * 4];
            *(float4*)b = *(const float4*)&Bs[k][tx * 4];
#pragma unroll
            for (int i = 0; i < 4; i++)
#pragma unroll
                for (int j = 0; j < 4; j++) acc[i][j] += a[i] * b[j];
        }
        __syncthreads();
    }
#pragma unroll
    for (int i = 0; i < 4; i++) {
        int r = ty * 4 + i;
        if (m0 + r < cnt) {
            int slot = base + m0 + r;
            int tok = g_tokmap[slot];
            float w = g_wmap[slot];
#pragma unroll
            for (int j = 0; j < 4; j++) {
                int c = tx * 4 + j;
                float v = acc[i][j] + eb2[e * P2 + c];
                atomicAdd(&g_routed[(size_t)tok * P2 + c], w * v);
            }
        }
    }
}

// ---------------- final gate + sigmoid (warp per token) ----------------
__global__ __launch_bounds__(256) void gate_kernel(const float* __restrict__ gW,
                                                   const float* __restrict__ gb,
                                                   float* __restrict__ out) {
    __shared__ __align__(16) float sW[128 * 64];  // 32KB
    for (int i = threadIdx.x; i < 128 * 64 / 4; i += 256)
        *(float4*)&sW[i * 4] = *(const float4*)&gW[i * 4];
    __syncthreads();
    int warp = threadIdx.x >> 5;
    int lane = threadIdx.x & 31;
    int tok = blockIdx.x * 8 + warp;
    if (tok >= B_TOK) return;
    const float* r = g_routed + (size_t)tok * P2;
    const float* s = g_sharedout + (size_t)tok * P2;
    float a0 = gb[lane], a1 = gb[lane + 32];
#pragma unroll 8
    for (int k = 0; k < 64; k++) {
        float c = r[k];
        a0 += c * sW[k * 64 + lane];
        a1 += c * sW[k * 64 + lane + 32];
    }
#pragma unroll 8
    for (int k = 0; k < 64; k++) {
        float c = s[k];
        a0 += c * sW[(64 + k) * 64 + lane];
        a1 += c * sW[(64 + k) * 64 + lane + 32];
    }
    out[(size_t)tok * P2 + lane]      = 1.0f / (1.0f + expf(-a0));
    out[(size_t)tok * P2 + lane + 32] = 1.0f / (1.0f + expf(-a1));
}

// ---------------- host launch sequence ----------------
extern "C" void kernel_launch(void* const* d_in, const int* in_sizes, int n_in,
                              void* d_out, int out_size) {
    const float* mm   = (const float*)d_in[0];
    const float* qf   = (const float*)d_in[1];
    const float* lng  = (const float*)d_in[2];
    const float* lnb  = (const float*)d_in[3];
    const float* pe   = (const float*)d_in[4];
    const float* qW   = (const float*)d_in[5];
    const float* qb   = (const float*)d_in[6];
    const float* eW1  = (const float*)d_in[7];
    const float* eb1  = (const float*)d_in[8];
    const float* eW2  = (const float*)d_in[9];
    const float* eb2  = (const float*)d_in[10];
    const float* sW1  = (const float*)d_in[11];
    const float* sb1  = (const float*)d_in[12];
    const float* sW2  = (const float*)d_in[13];
    const float* sb2  = (const float*)d_in[14];
    const float* gW   = (const float*)d_in[15];
    const float* gb   = (const float*)d_in[16];
    float* out = (float*)d_out;

    float *p_x, *p_q, *p_sh, *p_so;
    cudaGetSymbolAddress((void**)&p_x,  g_x);
    cudaGetSymbolAddress((void**)&p_q,  g_q);
    cudaGetSymbolAddress((void**)&p_sh, g_sh);
    cudaGetSymbolAddress((void**)&p_so, g_sharedout);

    reset_kernel<<<4096, 256>>>();
    ln_kernel<<<B_TOK / 8, 256>>>(mm, lng, lnb);
    pilot_norm_kernel<<<1, 1024>>>(pe);

    // qproj: [B,2048] @ [2048,1024] + b  (A = concat(x, query))
    gemm_ff<false, true><<<dim3(16, 256), 256>>>(p_x, qf, qW, qb, p_q, 1024, 2048);
    l2q_kernel<<<B_TOK / 8, 256>>>();
    router_kernel<<<B_TOK / 8, 256>>>();
    scan_kernel<<<1, 1>>>();
    fill_kernel<<<B_TOK / 256, 256>>>();

    // routed experts (sparse, per-expert segments)
    gemm_e1<<<dim3(16, B_TOK / 64, NE), 256>>>(eW1, eb1);
    gemm_e2<<<dim3(1, B_TOK / 64, NE), 256>>>(eW2, eb2);

    // shared expert
    gemm_ff<true, false><<<dim3(16, 256), 256>>>(p_x, nullptr, sW1, sb1, p_sh, 1024, 1024);
    gemm_ff<false, false><<<dim3(1, 256), 256>>>(p_sh, nullptr, sW2, sb2, p_so, 64, 1024);

    // gate + sigmoid -> output
    gate_kernel<<<B_TOK / 8, 256>>>(gW, gb, out);
}

// round 16
// speedup vs baseline: 1.8856x; 1.8798x over previous
#include <cuda_runtime.h>
#include <cuda_bf16.h>
#include <math.h>

// ---------------- problem constants ----------------
#define B_TOK 16384
#define H     1024
#define K2H   2048
#define P2    64
#define NE    8
#define EC    32
#define NSLOT (2*B_TOK)

// ---------------- device scratch ----------------
__device__ float         g_x[B_TOK * H];        // layernorm output (fp32, for sims)
__device__ __nv_bfloat16 g_xh[B_TOK * H];       // x hi
__device__ __nv_bfloat16 g_xl[B_TOK * H];       // x lo
__device__ __nv_bfloat16 g_qfh[B_TOK * H];      // query_feat hi
__device__ float         g_q[B_TOK * H];        // qproj output (only for ||q||)
__device__ float         g_qnorm[B_TOK];
__device__ float         g_pn[EC * H];          // normalized pilots
__device__ float         g_R[K2H * EC];         // R[k][ec] = qW[k,:] . pn[ec,:]
__device__ float         g_Rb[EC];              // qb . pn[ec]
__device__ int           g_te[B_TOK * 2];
__device__ float         g_tw[B_TOK * 2];
__device__ int           g_counts[NE];
__device__ int           g_base[NE];
__device__ int           g_cursor[NE];
__device__ int           g_tokmap[NSLOT];
__device__ int           g_slot[B_TOK * 2];
__device__ __nv_bfloat16 g_hhh[NSLOT * H];      // expert hidden hi
__device__ __nv_bfloat16 g_hhl[NSLOT * H];      // expert hidden lo
__device__ __nv_bfloat16 g_shh[B_TOK * H];      // shared hidden hi
__device__ __nv_bfloat16 g_shl[B_TOK * H];      // shared hidden lo
__device__ float         g_eout[NSLOT * P2];    // per-slot expert output (incl eb2)
__device__ float         g_so[B_TOK * P2];      // shared expert output (incl sb2)
// split weights
__device__ __nv_bfloat16 g_qWh[K2H * H];
__device__ __nv_bfloat16 g_eW1h[NE * H * H],  g_eW1l[NE * H * H];
__device__ __nv_bfloat16 g_eW2h[NE * H * P2], g_eW2l[NE * H * P2];
__device__ __nv_bfloat16 g_sW1h[H * H],       g_sW1l[H * H];
__device__ __nv_bfloat16 g_sW2h[H * P2],      g_sW2l[H * P2];

// ---------------- ptx helpers ----------------
__device__ __forceinline__ unsigned smem_u32(const void* p) {
    return (unsigned)__cvta_generic_to_shared(p);
}
__device__ __forceinline__ void ldsm_x4(unsigned* r, unsigned addr) {
    asm volatile("ldmatrix.sync.aligned.m8n8.x4.shared.b16 {%0,%1,%2,%3}, [%4];\n"
                 : "=r"(r[0]), "=r"(r[1]), "=r"(r[2]), "=r"(r[3]) : "r"(addr));
}
__device__ __forceinline__ void ldsm_x2t(unsigned* r, unsigned addr) {
    asm volatile("ldmatrix.sync.aligned.m8n8.x2.trans.shared.b16 {%0,%1}, [%2];\n"
                 : "=r"(r[0]), "=r"(r[1]) : "r"(addr));
}
__device__ __forceinline__ void mma_bf16(float* d, const unsigned* a, const unsigned* b) {
    asm volatile(
        "mma.sync.aligned.m16n8k16.row.col.f32.bf16.bf16.f32 "
        "{%0,%1,%2,%3}, {%4,%5,%6,%7}, {%8,%9}, {%0,%1,%2,%3};\n"
        : "+f"(d[0]), "+f"(d[1]), "+f"(d[2]), "+f"(d[3])
        : "r"(a[0]), "r"(a[1]), "r"(a[2]), "r"(a[3]), "r"(b[0]), "r"(b[1]));
}

// ---------------- reset ----------------
__global__ void reset_kernel() {
    if (threadIdx.x < NE) g_counts[threadIdx.x] = 0;
}

// ---------------- layernorm + hi/lo split (warp per row) ----------------
__global__ void ln_kernel(const float* __restrict__ mm,
                          const float* __restrict__ gamma,
                          const float* __restrict__ beta) {
    int warp = (blockIdx.x * blockDim.x + threadIdx.x) >> 5;
    int lane = threadIdx.x & 31;
    if (warp >= B_TOK) return;
    const float* row = mm + (size_t)warp * H;
    float s = 0.f, s2 = 0.f;
    for (int i = lane; i < H; i += 32) { float v = row[i]; s += v; s2 += v * v; }
    for (int o = 16; o; o >>= 1) {
        s  += __shfl_xor_sync(0xffffffff, s, o);
        s2 += __shfl_xor_sync(0xffffffff, s2, o);
    }
    float mean = s * (1.0f / H);
    float var  = s2 * (1.0f / H) - mean * mean;
    float inv  = rsqrtf(var + 1e-5f);
    size_t off = (size_t)warp * H;
    for (int i = lane; i < H; i += 32) {
        float v = (row[i] - mean) * inv * gamma[i] + beta[i];
        g_x[off + i] = v;
        __nv_bfloat16 h = __float2bfloat16(v);
        g_xh[off + i] = h;
        g_xl[off + i] = __float2bfloat16(v - __bfloat162float(h));
    }
}

// ---------------- fp32 -> bf16 hi (+ optional lo) ----------------
__global__ void split_kernel(const float* __restrict__ in,
                             __nv_bfloat16* __restrict__ oh,
                             __nv_bfloat16* __restrict__ ol, int n) {
    int i = blockIdx.x * 256 + threadIdx.x;
    if (i >= n) return;
    float v = in[i];
    __nv_bfloat16 h = __float2bfloat16(v);
    oh[i] = h;
    if (ol) ol[i] = __float2bfloat16(v - __bfloat162float(h));
}

// ---------------- pilot l2 normalize (warp per pilot) ----------------
__global__ void pilot_norm_kernel(const float* __restrict__ pe) {
    int warp = threadIdx.x >> 5;
    int lane = threadIdx.x & 31;
    const float* row = pe + (size_t)warp * H;
    float s2 = 0.f;
    for (int i = lane; i < H; i += 32) { float v = row[i]; s2 += v * v; }
    for (int o = 16; o; o >>= 1) s2 += __shfl_xor_sync(0xffffffff, s2, o);
    float inv = 1.0f / fmaxf(sqrtf(s2), 1e-12f);
    for (int i = lane; i < H; i += 32) g_pn[warp * H + i] = row[i] * inv;
}

// ---------------- R[k][ec] = qW[k,:] . pn[ec,:]  (fp32, warp per k-row) -----
__global__ __launch_bounds__(256) void r_kernel(const float* __restrict__ qW) {
    __shared__ float ps[EC][129];
    int warp = threadIdx.x >> 5, lane = threadIdx.x & 31;
    int k = blockIdx.x * 8 + warp;
    float acc[EC];
#pragma unroll
    for (int ec = 0; ec < EC; ec++) acc[ec] = 0.f;
    for (int ch = 0; ch < H; ch += 128) {
        __syncthreads();
        for (int i = threadIdx.x; i < EC * 128; i += 256) {
            int r = i >> 7, c = i & 127;
            ps[r][c] = g_pn[r * H + ch + c];
        }
        __syncthreads();
#pragma unroll
        for (int j = 0; j < 128; j += 32) {
            float wv = qW[(size_t)k * H + ch + j + lane];
#pragma unroll
            for (int ec = 0; ec < EC; ec++) acc[ec] += wv * ps[ec][j + lane];
        }
    }
#pragma unroll
    for (int ec = 0; ec < EC; ec++)
        for (int o = 16; o; o >>= 1) acc[ec] += __shfl_xor_sync(0xffffffff, acc[ec], o);
    if (lane < EC) { /* all lanes have all sums */ }
    g_R[k * EC + (threadIdx.x & 31)] = acc[threadIdx.x & 31];
}

// ---------------- Rb[ec] = qb . pn[ec]  (warp per ec) ----------------
__global__ void rb_kernel(const float* __restrict__ qb) {
    int ec = threadIdx.x >> 5, lane = threadIdx.x & 31;
    float s = 0.f;
    for (int i = lane; i < H; i += 32) s += qb[i] * g_pn[ec * H + i];
    for (int o = 16; o; o >>= 1) s += __shfl_xor_sync(0xffffffff, s, o);
    if (lane == 0) g_Rb[ec] = s;
}

// ---------------- ||q|| per token (warp per row) ----------------
__global__ void qnorm_kernel() {
    int warp = (blockIdx.x * blockDim.x + threadIdx.x) >> 5;
    int lane = threadIdx.x & 31;
    if (warp >= B_TOK) return;
    const float* row = g_q + (size_t)warp * H;
    float s2 = 0.f;
    for (int i = lane; i < H; i += 32) { float v = row[i]; s2 += v * v; }
    for (int o = 16; o; o >>= 1) s2 += __shfl_xor_sync(0xffffffff, s2, o);
    if (lane == 0) g_qnorm[warp] = fmaxf(sqrtf(s2), 1e-12f);
}

// ------ sims + softmax + top-2 router (fp32 ordering; warp per token) -------
__global__ __launch_bounds__(256) void sims_router_kernel(const float* __restrict__ qf) {
    __shared__ float Rs[256][33];
    int warp = threadIdx.x >> 5, lane = threadIdx.x & 31;
    int tok = blockIdx.x * 8 + warp;
    const float* xrow = g_x + (size_t)tok * H;
    const float* qrow = qf + (size_t)tok * H;
    float acc[EC];
#pragma unroll
    for (int ec = 0; ec < EC; ec++) acc[ec] = 0.f;
    for (int ch = 0; ch < K2H; ch += 256) {
        __syncthreads();
        for (int i = threadIdx.x; i < 256 * EC; i += 256) {
            int r = i >> 5, c = i & 31;
            Rs[r][c] = g_R[(ch + r) * EC + c];
        }
        __syncthreads();
#pragma unroll
        for (int j = 0; j < 256; j += 32) {
            int gh = ch + j + lane;
            float f = (gh < H) ? xrow[gh] : qrow[gh - H];
#pragma unroll
            for (int ec = 0; ec < EC; ec++) acc[ec] += f * Rs[j + lane][ec];
        }
    }
#pragma unroll
    for (int ec = 0; ec < EC; ec++)
        for (int o = 16; o; o >>= 1) acc[ec] += __shfl_xor_sync(0xffffffff, acc[ec], o);
    if (lane == 0) {
        float inv = 1.0f / g_qnorm[tok];
        float sc[NE];
#pragma unroll
        for (int e = 0; e < NE; e++) {
            float s = 0.f;
#pragma unroll
            for (int c = 0; c < 4; c++) s += acc[e * 4 + c] + g_Rb[e * 4 + c];
            sc[e] = s * 0.25f * inv;
        }
        float m = -1e30f;
#pragma unroll
        for (int e = 0; e < NE; e++) m = fmaxf(m, sc[e]);
        float p[NE], sum = 0.f;
#pragma unroll
        for (int e = 0; e < NE; e++) { p[e] = expf((sc[e] - m) * 10.f); sum += p[e]; }
        int i1 = 0;
#pragma unroll
        for (int e = 1; e < NE; e++) if (sc[e] > sc[i1]) i1 = e;
        int i2 = (i1 == 0) ? 1 : 0;
#pragma unroll
        for (int e = 0; e < NE; e++) if (e != i1 && sc[e] > sc[i2]) i2 = e;
        float w1 = p[i1] / sum, w2 = p[i2] / sum;
        float d = w1 + w2 + 1e-6f;
        w1 /= d; w2 /= d;
        g_te[tok * 2 + 0] = i1; g_te[tok * 2 + 1] = i2;
        g_tw[tok * 2 + 0] = w1; g_tw[tok * 2 + 1] = w2;
        atomicAdd(&g_counts[i1], 1);
        atomicAdd(&g_counts[i2], 1);
    }
}

// ---------------- scan + fill ----------------
__global__ void scan_kernel() {
    int b = 0;
    for (int e = 0; e < NE; e++) { g_base[e] = b; g_cursor[e] = b; b += g_counts[e]; }
}
__global__ void fill_kernel() {
    int b = blockIdx.x * blockDim.x + threadIdx.x;
    if (b >= B_TOK) return;
#pragma unroll
    for (int k = 0; k < 2; k++) {
        int e = g_te[b * 2 + k];
        int pos = atomicAdd(&g_cursor[e], 1);
        g_tokmap[pos] = b;
        g_slot[b * 2 + k] = pos;
    }
}

// =============================================================================
// bf16 mma.sync GEMM, 128x64 tile, BK=32, 256 threads (8 warps, 4x2 warp grid).
// C = A @ W (+bias), fp32 values represented as bf16 (hi, lo) pairs.
// NPASS==3: Ah*Wh + Ah*Wl + Al*Wh (fp32-class). NPASS==1: Ah*Wh.
// AMODE: 0 plain rows, 1 concat(xh|A2h) hi-only, 2 expert gather via tokmap,
//        3 expert sequential slot rows.  SPLITOUT: store bf16 hi/lo (else fp32).
// =============================================================================
template <int AMODE, int NPASS, bool RELU, bool SPLITOUT>
__global__ __launch_bounds__(256) void mma_gemm(
    const __nv_bfloat16* __restrict__ Ah, const __nv_bfloat16* __restrict__ Al,
    const __nv_bfloat16* __restrict__ A2h,
    const __nv_bfloat16* __restrict__ Wh, const __nv_bfloat16* __restrict__ Wl,
    const float* __restrict__ bias,
    float* __restrict__ Cf, __nv_bfloat16* __restrict__ Coh,
    __nv_bfloat16* __restrict__ Col, int N, int K)
{
    __shared__ __align__(16) __nv_bfloat16 As[128][40];
    __shared__ __align__(16) __nv_bfloat16 Bs[32][72];
    int m0 = blockIdx.y * 128, n0 = blockIdx.x * 64;
    int cnt = 0, base = 0;
    if (AMODE >= 2) {
        int e = blockIdx.z;
        cnt = g_counts[e]; base = g_base[e];
        if (m0 >= cnt) return;
        Wh += (size_t)e * K * N;
        if (NPASS == 3) Wl += (size_t)e * K * N;
        bias += e * N;
    }
    int tid = threadIdx.x;
    int lane = tid & 31, w = tid >> 5, wm = w & 3, wn = w >> 2;

    // A loader rows (fixed across k): rows tid>>2 and tid>>2 + 64
    int arow0 = tid >> 2;
    int acol  = (tid & 3) * 8;
    size_t aoff0, aoff1;
    if (AMODE == 2) {
        aoff0 = (size_t)g_tokmap[base + min(m0 + arow0,      cnt - 1)] * H;
        aoff1 = (size_t)g_tokmap[base + min(m0 + arow0 + 64, cnt - 1)] * H;
    } else if (AMODE == 3) {
        aoff0 = (size_t)(base + min(m0 + arow0,      cnt - 1)) * H;
        aoff1 = (size_t)(base + min(m0 + arow0 + 64, cnt - 1)) * H;
    } else {
        aoff0 = (size_t)(m0 + arow0) * H;
        aoff1 = (size_t)(m0 + arow0 + 64) * H;
    }
    int brow = tid >> 3;
    int bcol = (tid & 7) * 8;

    float acc[2][4][4];
#pragma unroll
    for (int mi = 0; mi < 2; mi++)
#pragma unroll
        for (int ni = 0; ni < 4; ni++)
#pragma unroll
            for (int c = 0; c < 4; c++) acc[mi][ni][c] = 0.f;

    for (int pass = 0; pass < NPASS; pass++) {
        const __nv_bfloat16* Ap = (NPASS == 3 && pass == 2) ? Al : Ah;
        const __nv_bfloat16* Wp = (NPASS == 3 && pass == 1) ? Wl : Wh;
        for (int kt = 0; kt < K; kt += 32) {
            uint4 v0, v1;
            if (AMODE == 1) {
                int kc = kt + acol;
                const __nv_bfloat16* src = (kc < H) ? Ah : A2h;
                int kcc = (kc < H) ? kc : kc - H;
                v0 = *(const uint4*)&src[aoff0 + kcc];
                v1 = *(const uint4*)&src[aoff1 + kcc];
            } else {
                v0 = *(const uint4*)&Ap[aoff0 + kt + acol];
                v1 = *(const uint4*)&Ap[aoff1 + kt + acol];
            }
            *(uint4*)&As[arow0][acol]      = v0;
            *(uint4*)&As[arow0 + 64][acol] = v1;
            *(uint4*)&Bs[brow][bcol] =
                *(const uint4*)&Wp[(size_t)(kt + brow) * N + n0 + bcol];
            __syncthreads();
#pragma unroll
            for (int ks = 0; ks < 2; ks++) {
                unsigned afrag[2][4], bfrag[4][2];
#pragma unroll
                for (int mi = 0; mi < 2; mi++)
                    ldsm_x4(afrag[mi], smem_u32(
                        &As[wm * 32 + mi * 16 + (lane & 15)][ks * 16 + (lane >> 4) * 8]));
#pragma unroll
                for (int ni = 0; ni < 4; ni++)
                    ldsm_x2t(bfrag[ni], smem_u32(
                        &Bs[ks * 16 + (lane & 15)][wn * 32 + ni * 8]));
#pragma unroll
                for (int mi = 0; mi < 2; mi++)
#pragma unroll
                    for (int ni = 0; ni < 4; ni++)
                        mma_bf16(acc[mi][ni], afrag[mi], bfrag[ni]);
            }
            __syncthreads();
        }
    }

    // epilogue
    int lr = lane >> 2, lc = (lane & 3) * 2;
#pragma unroll
    for (int mi = 0; mi < 2; mi++)
#pragma unroll
        for (int half = 0; half < 2; half++) {
            int rloc = wm * 32 + mi * 16 + lr + half * 8;
            size_t orow;
            if (AMODE >= 2) {
                if (m0 + rloc >= cnt) continue;
                orow = (size_t)(base + m0 + rloc);
            } else orow = (size_t)(m0 + rloc);
#pragma unroll
            for (int ni = 0; ni < 4; ni++)
#pragma unroll
                for (int cc = 0; cc < 2; cc++) {
                    int cloc = wn * 32 + ni * 8 + lc + cc;
                    float v = acc[mi][ni][half * 2 + cc] + bias[n0 + cloc];
                    if (RELU) v = fmaxf(v, 0.f);
                    size_t oidx = orow * (size_t)N + n0 + cloc;
                    if (SPLITOUT) {
                        __nv_bfloat16 hv = __float2bfloat16(v);
                        Coh[oidx] = hv;
                        Col[oidx] = __float2bfloat16(v - __bfloat162float(hv));
                    } else {
                        Cf[oidx] = v;
                    }
                }
        }
}

// ---------------- final gate + sigmoid (warp per token, slot gather) --------
__global__ __launch_bounds__(256) void gate_kernel(const float* __restrict__ gW,
                                                   const float* __restrict__ gb,
                                                   float* __restrict__ out) {
    __shared__ __align__(16) float sW[128 * 64];  // 32KB
    for (int i = threadIdx.x; i < 128 * 64 / 4; i += 256)
        *(float4*)&sW[i * 4] = *(const float4*)&gW[i * 4];
    __syncthreads();
    int warp = threadIdx.x >> 5;
    int lane = threadIdx.x & 31;
    int tok = blockIdx.x * 8 + warp;
    if (tok >= B_TOK) return;
    int s1 = g_slot[tok * 2 + 0], s2 = g_slot[tok * 2 + 1];
    float w1 = g_tw[tok * 2 + 0], w2 = g_tw[tok * 2 + 1];
    const float* r1 = g_eout + (size_t)s1 * P2;
    const float* r2 = g_eout + (size_t)s2 * P2;
    const float* s  = g_so   + (size_t)tok * P2;
    float a0 = gb[lane], a1 = gb[lane + 32];
#pragma unroll 8
    for (int k = 0; k < 64; k++) {
        float c = w1 * r1[k] + w2 * r2[k];
        a0 += c * sW[k * 64 + lane];
        a1 += c * sW[k * 64 + lane + 32];
    }
#pragma unroll 8
    for (int k = 0; k < 64; k++) {
        float c = s[k];
        a0 += c * sW[(64 + k) * 64 + lane];
        a1 += c * sW[(64 + k) * 64 + lane + 32];
    }
    out[(size_t)tok * P2 + lane]      = 1.0f / (1.0f + expf(-a0));
    out[(size_t)tok * P2 + lane + 32] = 1.0f / (1.0f + expf(-a1));
}

// ---------------- host launch sequence ----------------
extern "C" void kernel_launch(void* const* d_in, const int* in_sizes, int n_in,
                              void* d_out, int out_size) {
    const float* mm   = (const float*)d_in[0];
    const float* qf   = (const float*)d_in[1];
    const float* lng  = (const float*)d_in[2];
    const float* lnb  = (const float*)d_in[3];
    const float* pe   = (const float*)d_in[4];
    const float* qW   = (const float*)d_in[5];
    const float* qb   = (const float*)d_in[6];
    const float* eW1  = (const float*)d_in[7];
    const float* eb1  = (const float*)d_in[8];
    const float* eW2  = (const float*)d_in[9];
    const float* eb2  = (const float*)d_in[10];
    const float* sW1  = (const float*)d_in[11];
    const float* sb1  = (const float*)d_in[12];
    const float* sW2  = (const float*)d_in[13];
    const float* sb2  = (const float*)d_in[14];
    const float* gW   = (const float*)d_in[15];
    const float* gb   = (const float*)d_in[16];
    float* out = (float*)d_out;

    __nv_bfloat16 *p_xh, *p_xl, *p_qfh, *p_qWh, *p_eW1h, *p_eW1l, *p_eW2h,
        *p_eW2l, *p_sW1h, *p_sW1l, *p_sW2h, *p_sW2l, *p_hhh, *p_hhl, *p_shh, *p_shl;
    float *p_q, *p_eout, *p_so;
    cudaGetSymbolAddress((void**)&p_xh,   g_xh);
    cudaGetSymbolAddress((void**)&p_xl,   g_xl);
    cudaGetSymbolAddress((void**)&p_qfh,  g_qfh);
    cudaGetSymbolAddress((void**)&p_qWh,  g_qWh);
    cudaGetSymbolAddress((void**)&p_eW1h, g_eW1h);
    cudaGetSymbolAddress((void**)&p_eW1l, g_eW1l);
    cudaGetSymbolAddress((void**)&p_eW2h, g_eW2h);
    cudaGetSymbolAddress((void**)&p_eW2l, g_eW2l);
    cudaGetSymbolAddress((void**)&p_sW1h, g_sW1h);
    cudaGetSymbolAddress((void**)&p_sW1l, g_sW1l);
    cudaGetSymbolAddress((void**)&p_sW2h, g_sW2h);
    cudaGetSymbolAddress((void**)&p_sW2l, g_sW2l);
    cudaGetSymbolAddress((void**)&p_hhh,  g_hhh);
    cudaGetSymbolAddress((void**)&p_hhl,  g_hhl);
    cudaGetSymbolAddress((void**)&p_shh,  g_shh);
    cudaGetSymbolAddress((void**)&p_shl,  g_shl);
    cudaGetSymbolAddress((void**)&p_q,    g_q);
    cudaGetSymbolAddress((void**)&p_eout, g_eout);
    cudaGetSymbolAddress((void**)&p_so,   g_so);

    reset_kernel<<<1, 32>>>();
    ln_kernel<<<B_TOK / 8, 256>>>(mm, lng, lnb);
    pilot_norm_kernel<<<1, 1024>>>(pe);

    // weight / input splits (hi or hi+lo)
    split_kernel<<<(B_TOK * H + 255) / 256, 256>>>(qf, p_qfh, nullptr, B_TOK * H);
    split_kernel<<<(K2H * H + 255) / 256, 256>>>(qW, p_qWh, nullptr, K2H * H);
    split_kernel<<<(NE * H * H + 255) / 256, 256>>>(eW1, p_eW1h, p_eW1l, NE * H * H);
    split_kernel<<<(NE * H * P2 + 255) / 256, 256>>>(eW2, p_eW2h, p_eW2l, NE * H * P2);
    split_kernel<<<(H * H + 255) / 256, 256>>>(sW1, p_sW1h, p_sW1l, H * H);
    split_kernel<<<(H * P2 + 255) / 256, 256>>>(sW2, p_sW2h, p_sW2l, H * P2);

    // router precompute (fp32 exact-class ordering path)
    r_kernel<<<K2H / 8, 256>>>(qW);
    rb_kernel<<<1, 1024>>>(qb);

    // qproj (bf16 single-pass; only the norm is consumed)
    mma_gemm<1, 1, false, false><<<dim3(16, 128), 256>>>(
        p_xh, nullptr, p_qfh, p_qWh, nullptr, qb, p_q, nullptr, nullptr, H, K2H);
    qnorm_kernel<<<B_TOK / 8, 256>>>();
    sims_router_kernel<<<B_TOK / 8, 256>>>(qf);
    scan_kernel<<<1, 1>>>();
    fill_kernel<<<B_TOK / 256, 256>>>();

    // routed experts (3-pass split bf16)
    mma_gemm<2, 3, true, true><<<dim3(16, 128, NE), 256>>>(
        p_xh, p_xl, nullptr, p_eW1h, p_eW1l, eb1, nullptr, p_hhh, p_hhl, H, H);
    mma_gemm<3, 3, false, false><<<dim3(1, 128, NE), 256>>>(
        p_hhh, p_hhl, nullptr, p_eW2h, p_eW2l, eb2, p_eout, nullptr, nullptr, P2, H);

    // shared expert (3-pass split bf16)
    mma_gemm<0, 3, true, true><<<dim3(16, 128), 256>>>(
        p_xh, p_xl, nullptr, p_sW1h, p_sW1l, sb1, nullptr, p_shh, p_shl, H, H);
    mma_gemm<0, 3, false, false><<<dim3(1, 128), 256>>>(
        p_shh, p_shl, nullptr, p_sW2h, p_sW2l, sb2, p_so, nullptr, nullptr, P2, H);

    // gate + sigmoid -> output
    gate_kernel<<<B_TOK / 8, 256>>>(gW, gb, out);
}

// round 17
// speedup vs baseline: 2.8212x; 1.4962x over previous
#include <cuda_runtime.h>
#include <cuda_bf16.h>
#include <math.h>

// ---------------- problem constants ----------------
#define B_TOK 16384
#define H     1024
#define K2H   2048
#define P2    64
#define NE    8
#define EC    32
#define NSLOT (2*B_TOK)

// ---------------- device scratch ----------------
__device__ float         g_x[B_TOK * H];        // layernorm output (fp32, for sims)
__device__ __nv_bfloat16 g_xh[B_TOK * H];       // x hi
__device__ __nv_bfloat16 g_xl[B_TOK * H];       // x lo
__device__ __nv_bfloat16 g_qfh[B_TOK * H];      // query_feat hi
__device__ float         g_q[B_TOK * H];        // qproj output (only for ||q||)
__device__ float         g_qnorm[B_TOK];
__device__ float         g_pn[EC * H];          // normalized pilots
__device__ float         g_R[K2H * EC];         // R[k][ec] = qW[k,:] . pn[ec,:]
__device__ float         g_Rb[EC];              // qb . pn[ec]
__device__ int           g_te[B_TOK * 2];
__device__ float         g_tw[B_TOK * 2];
__device__ int           g_counts[NE];
__device__ int           g_base[NE];
__device__ int           g_cursor[NE];
__device__ int           g_tokmap[NSLOT];
__device__ int           g_slot[B_TOK * 2];
__device__ __nv_bfloat16 g_hhh[NSLOT * H];      // expert hidden hi
__device__ __nv_bfloat16 g_hhl[NSLOT * H];      // expert hidden lo
__device__ __nv_bfloat16 g_shh[B_TOK * H];      // shared hidden hi
__device__ __nv_bfloat16 g_shl[B_TOK * H];      // shared hidden lo
__device__ float         g_eout[NSLOT * P2];    // per-slot expert output (incl eb2)
__device__ float         g_so[B_TOK * P2];      // shared expert output (incl sb2)
// split weights
__device__ __nv_bfloat16 g_qWh[K2H * H];
__device__ __nv_bfloat16 g_eW1h[NE * H * H],  g_eW1l[NE * H * H];
__device__ __nv_bfloat16 g_eW2h[NE * H * P2], g_eW2l[NE * H * P2];
__device__ __nv_bfloat16 g_sW1h[H * H],       g_sW1l[H * H];
__device__ __nv_bfloat16 g_sW2h[H * P2],      g_sW2l[H * P2];

// ---------------- ptx helpers ----------------
__device__ __forceinline__ unsigned smem_u32(const void* p) {
    return (unsigned)__cvta_generic_to_shared(p);
}
__device__ __forceinline__ void ldsm_x4(unsigned* r, unsigned addr) {
    asm volatile("ldmatrix.sync.aligned.m8n8.x4.shared.b16 {%0,%1,%2,%3}, [%4];\n"
                 : "=r"(r[0]), "=r"(r[1]), "=r"(r[2]), "=r"(r[3]) : "r"(addr));
}
__device__ __forceinline__ void ldsm_x2t(unsigned* r, unsigned addr) {
    asm volatile("ldmatrix.sync.aligned.m8n8.x2.trans.shared.b16 {%0,%1}, [%2];\n"
                 : "=r"(r[0]), "=r"(r[1]) : "r"(addr));
}
__device__ __forceinline__ void mma_bf16(float* d, const unsigned* a, const unsigned* b) {
    asm volatile(
        "mma.sync.aligned.m16n8k16.row.col.f32.bf16.bf16.f32 "
        "{%0,%1,%2,%3}, {%4,%5,%6,%7}, {%8,%9}, {%0,%1,%2,%3};\n"
        : "+f"(d[0]), "+f"(d[1]), "+f"(d[2]), "+f"(d[3])
        : "r"(a[0]), "r"(a[1]), "r"(a[2]), "r"(a[3]), "r"(b[0]), "r"(b[1]));
}
__device__ __forceinline__ void cp16(__nv_bfloat16* s, const __nv_bfloat16* g) {
    asm volatile("cp.async.cg.shared.global [%0], [%1], 16;\n"
                 :: "r"(smem_u32(s)), "l"(g));
}
__device__ __forceinline__ void cp_commit() {
    asm volatile("cp.async.commit_group;\n");
}

// ---------------- reset ----------------
__global__ void reset_kernel() {
    if (threadIdx.x < NE) g_counts[threadIdx.x] = 0;
}

// ---------------- layernorm + hi/lo split (warp per row) ----------------
__global__ void ln_kernel(const float* __restrict__ mm,
                          const float* __restrict__ gamma,
                          const float* __restrict__ beta) {
    int warp = (blockIdx.x * blockDim.x + threadIdx.x) >> 5;
    int lane = threadIdx.x & 31;
    if (warp >= B_TOK) return;
    const float* row = mm + (size_t)warp * H;
    float s = 0.f, s2 = 0.f;
    for (int i = lane; i < H; i += 32) { float v = row[i]; s += v; s2 += v * v; }
    for (int o = 16; o; o >>= 1) {
        s  += __shfl_xor_sync(0xffffffff, s, o);
        s2 += __shfl_xor_sync(0xffffffff, s2, o);
    }
    float mean = s * (1.0f / H);
    float var  = s2 * (1.0f / H) - mean * mean;
    float inv  = rsqrtf(var + 1e-5f);
    size_t off = (size_t)warp * H;
    for (int i = lane; i < H; i += 32) {
        float v = (row[i] - mean) * inv * gamma[i] + beta[i];
        g_x[off + i] = v;
        __nv_bfloat16 h = __float2bfloat16(v);
        g_xh[off + i] = h;
        g_xl[off + i] = __float2bfloat16(v - __bfloat162float(h));
    }
}

// ---------------- fp32 -> bf16 hi (+ optional lo), 4 elem/thread ------------
__global__ void split_kernel(const float* __restrict__ in,
                             __nv_bfloat16* __restrict__ oh,
                             __nv_bfloat16* __restrict__ ol, int n) {
    int i = (blockIdx.x * 256 + threadIdx.x) * 4;
    if (i >= n) return;
    float4 v = *(const float4*)&in[i];
    __nv_bfloat16 h0 = __float2bfloat16(v.x), h1 = __float2bfloat16(v.y);
    __nv_bfloat16 h2 = __float2bfloat16(v.z), h3 = __float2bfloat16(v.w);
    __nv_bfloat162 ph0(h0, h1), ph1(h2, h3);
    *(uint2*)&oh[i] = make_uint2(*(unsigned*)&ph0, *(unsigned*)&ph1);
    if (ol) {
        __nv_bfloat162 pl0(__float2bfloat16(v.x - __bfloat162float(h0)),
                           __float2bfloat16(v.y - __bfloat162float(h1)));
        __nv_bfloat162 pl1(__float2bfloat16(v.z - __bfloat162float(h2)),
                           __float2bfloat16(v.w - __bfloat162float(h3)));
        *(uint2*)&ol[i] = make_uint2(*(unsigned*)&pl0, *(unsigned*)&pl1);
    }
}

// ---------------- pilot l2 normalize (warp per pilot) ----------------
__global__ void pilot_norm_kernel(const float* __restrict__ pe) {
    int warp = threadIdx.x >> 5;
    int lane = threadIdx.x & 31;
    const float* row = pe + (size_t)warp * H;
    float s2 = 0.f;
    for (int i = lane; i < H; i += 32) { float v = row[i]; s2 += v * v; }
    for (int o = 16; o; o >>= 1) s2 += __shfl_xor_sync(0xffffffff, s2, o);
    float inv = 1.0f / fmaxf(sqrtf(s2), 1e-12f);
    for (int i = lane; i < H; i += 32) g_pn[warp * H + i] = row[i] * inv;
}

// ---------------- R[k][ec] = qW[k,:] . pn[ec,:]  (fp32, warp per k-row) -----
__global__ __launch_bounds__(256) void r_kernel(const float* __restrict__ qW) {
    __shared__ float ps[EC][129];
    int warp = threadIdx.x >> 5, lane = threadIdx.x & 31;
    int k = blockIdx.x * 8 + warp;
    float acc[EC];
#pragma unroll
    for (int ec = 0; ec < EC; ec++) acc[ec] = 0.f;
    for (int ch = 0; ch < H; ch += 128) {
        __syncthreads();
        for (int i = threadIdx.x; i < EC * 128; i += 256) {
            int r = i >> 7, c = i & 127;
            ps[r][c] = g_pn[r * H + ch + c];
        }
        __syncthreads();
#pragma unroll
        for (int j = 0; j < 128; j += 32) {
            float wv = qW[(size_t)k * H + ch + j + lane];
#pragma unroll
            for (int ec = 0; ec < EC; ec++) acc[ec] += wv * ps[ec][j + lane];
        }
    }
#pragma unroll
    for (int ec = 0; ec < EC; ec++)
        for (int o = 16; o; o >>= 1) acc[ec] += __shfl_xor_sync(0xffffffff, acc[ec], o);
    g_R[k * EC + lane] = acc[lane];
}

// ---------------- Rb[ec] = qb . pn[ec]  (warp per ec) ----------------
__global__ void rb_kernel(const float* __restrict__ qb) {
    int ec = threadIdx.x >> 5, lane = threadIdx.x & 31;
    float s = 0.f;
    for (int i = lane; i < H; i += 32) s += qb[i] * g_pn[ec * H + i];
    for (int o = 16; o; o >>= 1) s += __shfl_xor_sync(0xffffffff, s, o);
    if (lane == 0) g_Rb[ec] = s;
}

// ---------------- ||q|| per token (warp per row) ----------------
__global__ void qnorm_kernel() {
    int warp = (blockIdx.x * blockDim.x + threadIdx.x) >> 5;
    int lane = threadIdx.x & 31;
    if (warp >= B_TOK) return;
    const float* row = g_q + (size_t)warp * H;
    float s2 = 0.f;
    for (int i = lane; i < H; i += 32) { float v = row[i]; s2 += v * v; }
    for (int o = 16; o; o >>= 1) s2 += __shfl_xor_sync(0xffffffff, s2, o);
    if (lane == 0) g_qnorm[warp] = fmaxf(sqrtf(s2), 1e-12f);
}

// ------ sims + softmax + top-2 router (fp32 ordering; warp per token) -------
__global__ __launch_bounds__(256) void sims_router_kernel(const float* __restrict__ qf) {
    __shared__ float Rs[256][33];
    int warp = threadIdx.x >> 5, lane = threadIdx.x & 31;
    int tok = blockIdx.x * 8 + warp;
    const float* xrow = g_x + (size_t)tok * H;
    const float* qrow = qf + (size_t)tok * H;
    float acc[EC];
#pragma unroll
    for (int ec = 0; ec < EC; ec++) acc[ec] = 0.f;
    for (int ch = 0; ch < K2H; ch += 256) {
        __syncthreads();
        for (int i = threadIdx.x; i < 256 * EC; i += 256) {
            int r = i >> 5, c = i & 31;
            Rs[r][c] = g_R[(ch + r) * EC + c];
        }
        __syncthreads();
#pragma unroll
        for (int j = 0; j < 256; j += 32) {
            int gh = ch + j + lane;
            float f = (gh < H) ? xrow[gh] : qrow[gh - H];
#pragma unroll
            for (int ec = 0; ec < EC; ec++) acc[ec] += f * Rs[j + lane][ec];
        }
    }
#pragma unroll
    for (int ec = 0; ec < EC; ec++)
        for (int o = 16; o; o >>= 1) acc[ec] += __shfl_xor_sync(0xffffffff, acc[ec], o);
    if (lane == 0) {
        float inv = 1.0f / g_qnorm[tok];
        float sc[NE];
#pragma unroll
        for (int e = 0; e < NE; e++) {
            float s = 0.f;
#pragma unroll
            for (int c = 0; c < 4; c++) s += acc[e * 4 + c] + g_Rb[e * 4 + c];
            sc[e] = s * 0.25f * inv;
        }
        float m = -1e30f;
#pragma unroll
        for (int e = 0; e < NE; e++) m = fmaxf(m, sc[e]);
        float p[NE], sum = 0.f;
#pragma unroll
        for (int e = 0; e < NE; e++) { p[e] = expf((sc[e] - m) * 10.f); sum += p[e]; }
        int i1 = 0;
#pragma unroll
        for (int e = 1; e < NE; e++) if (sc[e] > sc[i1]) i1 = e;
        int i2 = (i1 == 0) ? 1 : 0;
#pragma unroll
        for (int e = 0; e < NE; e++) if (e != i1 && sc[e] > sc[i2]) i2 = e;
        float w1 = p[i1] / sum, w2 = p[i2] / sum;
        float d = w1 + w2 + 1e-6f;
        w1 /= d; w2 /= d;
        g_te[tok * 2 + 0] = i1; g_te[tok * 2 + 1] = i2;
        g_tw[tok * 2 + 0] = w1; g_tw[tok * 2 + 1] = w2;
        atomicAdd(&g_counts[i1], 1);
        atomicAdd(&g_counts[i2], 1);
    }
}

// ---------------- scan + fill ----------------
__global__ void scan_kernel() {
    int b = 0;
    for (int e = 0; e < NE; e++) { g_base[e] = b; g_cursor[e] = b; b += g_counts[e]; }
}
__global__ void fill_kernel() {
    int b = blockIdx.x * blockDim.x + threadIdx.x;
    if (b >= B_TOK) return;
#pragma unroll
    for (int k = 0; k < 2; k++) {
        int e = g_te[b * 2 + k];
        int pos = atomicAdd(&g_cursor[e], 1);
        g_tokmap[pos] = b;
        g_slot[b * 2 + k] = pos;
    }
}

// =============================================================================
// Fused-pass, cp.async double-buffered bf16 mma GEMM.
// BM=128, BK=32, 256 threads (8 warps: 4 row x 2 col; warp tile 32 x BN/2).
// Per k-tile, Ah/Al/Wh/Wl tiles are loaded ONCE; all NPASS mma passes issue
// from the same smem tiles (hi*hi + hi*lo + lo*hi).
// AMODE: 0 plain rows, 1 concat(xh|A2h) hi-only, 2 expert gather via tokmap,
//        3 expert sequential slot rows.  SPLITOUT: bf16 hi/lo out (else fp32).
// =============================================================================
template <int AMODE, int NPASS, bool RELU, bool SPLITOUT, int BN>
__global__ __launch_bounds__(256) void mma_gemm(
    const __nv_bfloat16* __restrict__ Ah, const __nv_bfloat16* __restrict__ Al,
    const __nv_bfloat16* __restrict__ A2h,
    const __nv_bfloat16* __restrict__ Wh, const __nv_bfloat16* __restrict__ Wl,
    const float* __restrict__ bias,
    float* __restrict__ Cf, __nv_bfloat16* __restrict__ Coh,
    __nv_bfloat16* __restrict__ Col, int N, int K)
{
    constexpr int AST = 40;            // A smem row stride (elems)
    constexpr int BNP = BN + 8;        // B smem row stride (elems)
    constexpr int NPL = (NPASS == 3) ? 2 : 1;
    constexpr int A_SZ = 128 * AST;
    constexpr int B_SZ = 32 * BNP;
    constexpr int STAGE = NPL * (A_SZ + B_SZ);
    constexpr int NI = BN / 16;        // n8 blocks per warp

    extern __shared__ __align__(16) __nv_bfloat16 sm[];

    int m0 = blockIdx.y * 128, n0 = blockIdx.x * BN;
    int cnt = 0, base = 0;
    if (AMODE >= 2) {
        int e = blockIdx.z;
        cnt = g_counts[e]; base = g_base[e];
        if (m0 >= cnt) return;
        Wh += (size_t)e * K * N;
        if (NPASS == 3) Wl += (size_t)e * K * N;
        bias += e * N;
    }
    int tid = threadIdx.x;
    int lane = tid & 31, w = tid >> 5, wm = w & 3, wn = w >> 2;

    // A loader mapping: rows tid>>2 and tid>>2+64, col quad (tid&3)*8
    int arow0 = tid >> 2;
    int acol  = (tid & 3) * 8;
    size_t aoff0, aoff1;
    if (AMODE == 2) {
        aoff0 = (size_t)g_tokmap[base + min(m0 + arow0,      cnt - 1)] * H;
        aoff1 = (size_t)g_tokmap[base + min(m0 + arow0 + 64, cnt - 1)] * H;
    } else if (AMODE == 3) {
        aoff0 = (size_t)(base + min(m0 + arow0,      cnt - 1)) * H;
        aoff1 = (size_t)(base + min(m0 + arow0 + 64, cnt - 1)) * H;
    } else {
        aoff0 = (size_t)(m0 + arow0) * H;
        aoff1 = (size_t)(m0 + arow0 + 64) * H;
    }
    // B loader mapping
    int brow = (BN == 128) ? (tid >> 4) : (tid >> 3);
    int bcol = (BN == 128) ? ((tid & 15) * 8) : ((tid & 7) * 8);

    auto issue_tile = [&](int kt, int st) {
        __nv_bfloat16* As_h = sm + st * STAGE;
        __nv_bfloat16* Bs_h = sm + st * STAGE + NPL * A_SZ;
        // A hi
        if (AMODE == 1) {
            int kc = kt + acol;
            const __nv_bfloat16* src = (kc < H) ? Ah : A2h;
            int kcc = (kc < H) ? kc : kc - H;
            cp16(As_h + arow0 * AST + acol,        src + aoff0 + kcc);
            cp16(As_h + (arow0 + 64) * AST + acol, src + aoff1 + kcc);
        } else {
            cp16(As_h + arow0 * AST + acol,        Ah + aoff0 + kt + acol);
            cp16(As_h + (arow0 + 64) * AST + acol, Ah + aoff1 + kt + acol);
        }
        if (NPASS == 3) {
            __nv_bfloat16* As_l = As_h + A_SZ;
            cp16(As_l + arow0 * AST + acol,        Al + aoff0 + kt + acol);
            cp16(As_l + (arow0 + 64) * AST + acol, Al + aoff1 + kt + acol);
        }
        // B hi (+lo)
        if (BN == 128) {
            cp16(Bs_h + brow * BNP + bcol,        Wh + (size_t)(kt + brow) * N + n0 + bcol);
            cp16(Bs_h + (brow + 16) * BNP + bcol, Wh + (size_t)(kt + brow + 16) * N + n0 + bcol);
            if (NPASS == 3) {
                __nv_bfloat16* Bs_l = Bs_h + B_SZ;
                cp16(Bs_l + brow * BNP + bcol,        Wl + (size_t)(kt + brow) * N + n0 + bcol);
                cp16(Bs_l + (brow + 16) * BNP + bcol, Wl + (size_t)(kt + brow + 16) * N + n0 + bcol);
            }
        } else {
            cp16(Bs_h + brow * BNP + bcol, Wh + (size_t)(kt + brow) * N + n0 + bcol);
            if (NPASS == 3) {
                __nv_bfloat16* Bs_l = Bs_h + B_SZ;
                cp16(Bs_l + brow * BNP + bcol, Wl + (size_t)(kt + brow) * N + n0 + bcol);
            }
        }
        cp_commit();
    };

    float acc[2][NI][4];
#pragma unroll
    for (int mi = 0; mi < 2; mi++)
#pragma unroll
        for (int ni = 0; ni < NI; ni++)
#pragma unroll
            for (int c = 0; c < 4; c++) acc[mi][ni][c] = 0.f;

    int T = K / 32;
    issue_tile(0, 0);
    for (int t = 0; t < T; t++) {
        if (t + 1 < T) issue_tile((t + 1) * 32, (t + 1) & 1);
        if (t + 1 < T) asm volatile("cp.async.wait_group 1;\n");
        else           asm volatile("cp.async.wait_group 0;\n");
        __syncthreads();

        int st = t & 1;
        const __nv_bfloat16* As_h = sm + st * STAGE;
        const __nv_bfloat16* As_l = As_h + A_SZ;
        const __nv_bfloat16* Bs_h = sm + st * STAGE + NPL * A_SZ;
        const __nv_bfloat16* Bs_l = Bs_h + B_SZ;
#pragma unroll
        for (int ks = 0; ks < 2; ks++) {
            unsigned afh[2][4], afl[2][4];
#pragma unroll
            for (int mi = 0; mi < 2; mi++)
                ldsm_x4(afh[mi], smem_u32(
                    As_h + (wm * 32 + mi * 16 + (lane & 15)) * AST + ks * 16 + (lane >> 4) * 8));
            if (NPASS == 3) {
#pragma unroll
                for (int mi = 0; mi < 2; mi++)
                    ldsm_x4(afl[mi], smem_u32(
                        As_l + (wm * 32 + mi * 16 + (lane & 15)) * AST + ks * 16 + (lane >> 4) * 8));
            }
#pragma unroll
            for (int ni = 0; ni < NI; ni++) {
                unsigned bh[2], bl[2];
                ldsm_x2t(bh, smem_u32(
                    Bs_h + (ks * 16 + (lane & 15)) * BNP + wn * (BN / 2) + ni * 8));
                if (NPASS == 3)
                    ldsm_x2t(bl, smem_u32(
                        Bs_l + (ks * 16 + (lane & 15)) * BNP + wn * (BN / 2) + ni * 8));
#pragma unroll
                for (int mi = 0; mi < 2; mi++) {
                    mma_bf16(acc[mi][ni], afh[mi], bh);
                    if (NPASS == 3) {
                        mma_bf16(acc[mi][ni], afh[mi], bl);
                        mma_bf16(acc[mi][ni], afl[mi], bh);
                    }
                }
            }
        }
        __syncthreads();
    }

    // epilogue
    int lr = lane >> 2, lc = (lane & 3) * 2;
#pragma unroll
    for (int mi = 0; mi < 2; mi++)
#pragma unroll
        for (int half = 0; half < 2; half++) {
            int rloc = wm * 32 + mi * 16 + lr + half * 8;
            size_t orow;
            if (AMODE >= 2) {
                if (m0 + rloc >= cnt) continue;
                orow = (size_t)(base + m0 + rloc);
            } else orow = (size_t)(m0 + rloc);
#pragma unroll
            for (int ni = 0; ni < NI; ni++)
#pragma unroll
                for (int cc = 0; cc < 2; cc++) {
                    int cloc = wn * (BN / 2) + ni * 8 + lc + cc;
                    float v = acc[mi][ni][half * 2 + cc] + bias[n0 + cloc];
                    if (RELU) v = fmaxf(v, 0.f);
                    size_t oidx = orow * (size_t)N + n0 + cloc;
                    if (SPLITOUT) {
                        __nv_bfloat16 hv = __float2bfloat16(v);
                        Coh[oidx] = hv;
                        Col[oidx] = __float2bfloat16(v - __bfloat162float(hv));
                    } else {
                        Cf[oidx] = v;
                    }
                }
        }
}

// ---------------- final gate + sigmoid (warp per token, slot gather) --------
__global__ __launch_bounds__(256) void gate_kernel(const float* __restrict__ gW,
                                                   const float* __restrict__ gb,
                                                   float* __restrict__ out) {
    __shared__ __align__(16) float sW[128 * 64];  // 32KB
    for (int i = threadIdx.x; i < 128 * 64 / 4; i += 256)
        *(float4*)&sW[i * 4] = *(const float4*)&gW[i * 4];
    __syncthreads();
    int warp = threadIdx.x >> 5;
    int lane = threadIdx.x & 31;
    int tok = blockIdx.x * 8 + warp;
    if (tok >= B_TOK) return;
    int s1 = g_slot[tok * 2 + 0], s2 = g_slot[tok * 2 + 1];
    float w1 = g_tw[tok * 2 + 0], w2 = g_tw[tok * 2 + 1];
    const float* r1 = g_eout + (size_t)s1 * P2;
    const float* r2 = g_eout + (size_t)s2 * P2;
    const float* s  = g_so   + (size_t)tok * P2;
    float a0 = gb[lane], a1 = gb[lane + 32];
#pragma unroll 8
    for (int k = 0; k < 64; k++) {
        float c = w1 * r1[k] + w2 * r2[k];
        a0 += c * sW[k * 64 + lane];
        a1 += c * sW[k * 64 + lane + 32];
    }
#pragma unroll 8
    for (int k = 0; k < 64; k++) {
        float c = s[k];
        a0 += c * sW[(64 + k) * 64 + lane];
        a1 += c * sW[(64 + k) * 64 + lane + 32];
    }
    out[(size_t)tok * P2 + lane]      = 1.0f / (1.0f + expf(-a0));
    out[(size_t)tok * P2 + lane + 32] = 1.0f / (1.0f + expf(-a1));
}

// ---------------- host launch sequence ----------------
extern "C" void kernel_launch(void* const* d_in, const int* in_sizes, int n_in,
                              void* d_out, int out_size) {
    const float* mm   = (const float*)d_in[0];
    const float* qf   = (const float*)d_in[1];
    const float* lng  = (const float*)d_in[2];
    const float* lnb  = (const float*)d_in[3];
    const float* pe   = (const float*)d_in[4];
    const float* qW   = (const float*)d_in[5];
    const float* qb   = (const float*)d_in[6];
    const float* eW1  = (const float*)d_in[7];
    const float* eb1  = (const float*)d_in[8];
    const float* eW2  = (const float*)d_in[9];
    const float* eb2  = (const float*)d_in[10];
    const float* sW1  = (const float*)d_in[11];
    const float* sb1  = (const float*)d_in[12];
    const float* sW2  = (const float*)d_in[13];
    const float* sb2  = (const float*)d_in[14];
    const float* gW   = (const float*)d_in[15];
    const float* gb   = (const float*)d_in[16];
    float* out = (float*)d_out;

    __nv_bfloat16 *p_xh, *p_xl, *p_qfh, *p_qWh, *p_eW1h, *p_eW1l, *p_eW2h,
        *p_eW2l, *p_sW1h, *p_sW1l, *p_sW2h, *p_sW2l, *p_hhh, *p_hhl, *p_shh, *p_shl;
    float *p_q, *p_eout, *p_so;
    cudaGetSymbolAddress((void**)&p_xh,   g_xh);
    cudaGetSymbolAddress((void**)&p_xl,   g_xl);
    cudaGetSymbolAddress((void**)&p_qfh,  g_qfh);
    cudaGetSymbolAddress((void**)&p_qWh,  g_qWh);
    cudaGetSymbolAddress((void**)&p_eW1h, g_eW1h);
    cudaGetSymbolAddress((void**)&p_eW1l, g_eW1l);
    cudaGetSymbolAddress((void**)&p_eW2h, g_eW2h);
    cudaGetSymbolAddress((void**)&p_eW2l, g_eW2l);
    cudaGetSymbolAddress((void**)&p_sW1h, g_sW1h);
    cudaGetSymbolAddress((void**)&p_sW1l, g_sW1l);
    cudaGetSymbolAddress((void**)&p_sW2h, g_sW2h);
    cudaGetSymbolAddress((void**)&p_sW2l, g_sW2l);
    cudaGetSymbolAddress((void**)&p_hhh,  g_hhh);
    cudaGetSymbolAddress((void**)&p_hhl,  g_hhl);
    cudaGetSymbolAddress((void**)&p_shh,  g_shh);
    cudaGetSymbolAddress((void**)&p_shl,  g_shl);
    cudaGetSymbolAddress((void**)&p_q,    g_q);
    cudaGetSymbolAddress((void**)&p_eout, g_eout);
    cudaGetSymbolAddress((void**)&p_so,   g_so);

    // dynamic smem sizes: 2 stages * NPL*(A+B) * 2 bytes
    const int smem_31 = 2 * 2 * (128 * 40 + 32 * 136) * 2;  // NPASS3 BN128 = 75776
    const int smem_36 = 2 * 2 * (128 * 40 + 32 * 72)  * 2;  // NPASS3 BN64  = 59392
    const int smem_11 = 2 * 1 * (128 * 40 + 32 * 136) * 2;  // NPASS1 BN128 = 37888
    cudaFuncSetAttribute(mma_gemm<1, 1, false, false, 128>,
                         cudaFuncAttributeMaxDynamicSharedMemorySize, smem_11);
    cudaFuncSetAttribute(mma_gemm<2, 3, true, true, 128>,
                         cudaFuncAttributeMaxDynamicSharedMemorySize, smem_31);
    cudaFuncSetAttribute(mma_gemm<3, 3, false, false, 64>,
                         cudaFuncAttributeMaxDynamicSharedMemorySize, smem_36);
    cudaFuncSetAttribute(mma_gemm<0, 3, true, true, 128>,
                         cudaFuncAttributeMaxDynamicSharedMemorySize, smem_31);
    cudaFuncSetAttribute(mma_gemm<0, 3, false, false, 64>,
                         cudaFuncAttributeMaxDynamicSharedMemorySize, smem_36);

    reset_kernel<<<1, 32>>>();
    ln_kernel<<<B_TOK / 8, 256>>>(mm, lng, lnb);
    pilot_norm_kernel<<<1, 1024>>>(pe);

    // weight / input splits (hi or hi+lo), 4 elem/thread
    split_kernel<<<(B_TOK * H / 4 + 255) / 256, 256>>>(qf, p_qfh, nullptr, B_TOK * H);
    split_kernel<<<(K2H * H / 4 + 255) / 256, 256>>>(qW, p_qWh, nullptr, K2H * H);
    split_kernel<<<(NE * H * H / 4 + 255) / 256, 256>>>(eW1, p_eW1h, p_eW1l, NE * H * H);
    split_kernel<<<(NE * H * P2 / 4 + 255) / 256, 256>>>(eW2, p_eW2h, p_eW2l, NE * H * P2);
    split_kernel<<<(H * H / 4 + 255) / 256, 256>>>(sW1, p_sW1h, p_sW1l, H * H);
    split_kernel<<<(H * P2 / 4 + 255) / 256, 256>>>(sW2, p_sW2h, p_sW2l, H * P2);

    // router precompute (fp32 exact-class ordering path)
    r_kernel<<<K2H / 8, 256>>>(qW);
    rb_kernel<<<1, 1024>>>(qb);

    // qproj (bf16 single-pass; only the norm is consumed)
    mma_gemm<1, 1, false, false, 128><<<dim3(8, 128), 256, smem_11>>>(
        p_xh, nullptr, p_qfh, p_qWh, nullptr, qb, p_q, nullptr, nullptr, H, K2H);
    qnorm_kernel<<<B_TOK / 8, 256>>>();
    sims_router_kernel<<<B_TOK / 8, 256>>>(qf);
    scan_kernel<<<1, 1>>>();
    fill_kernel<<<B_TOK / 256, 256>>>();

    // routed experts (fused 3-pass split bf16)
    mma_gemm<2, 3, true, true, 128><<<dim3(8, 128, NE), 256, smem_31>>>(
        p_xh, p_xl, nullptr, p_eW1h, p_eW1l, eb1, nullptr, p_hhh, p_hhl, H, H);
    mma_gemm<3, 3, false, false, 64><<<dim3(1, 128, NE), 256, smem_36>>>(
        p_hhh, p_hhl, nullptr, p_eW2h, p_eW2l, eb2, p_eout, nullptr, nullptr, P2, H);

    // shared expert (fused 3-pass split bf16)
    mma_gemm<0, 3, true, true, 128><<<dim3(8, 128), 256, smem_31>>>(
        p_xh, p_xl, nullptr, p_sW1h, p_sW1l, sb1, nullptr, p_shh, p_shl, H, H);
    mma_gemm<0, 3, false, false, 64><<<dim3(1, 128), 256, smem_36>>>(
        p_shh, p_shl, nullptr, p_sW2h, p_sW2l, sb2, p_so, nullptr, nullptr, P2, H);

    // gate + sigmoid -> output
    gate_kernel<<<B_TOK / 8, 256>>>(gW, gb, out);
}